// round 8
// baseline (speedup 1.0000x reference)
#include <cuda_runtime.h>
#include <cuda_bf16.h>
#include <math.h>
#include <stdint.h>

#define SEQ 2048
#define HID 2048
#define NH  16
#define NKV 8
#define HD  128

// ---------------------------------------------------------------------------
// Scratch (allocation-free: __device__ globals)
// ---------------------------------------------------------------------------
__device__ __nv_bfloat16 g_xh[(size_t)SEQ * HID],       g_xl[(size_t)SEQ * HID];
__device__ __nv_bfloat16 g_wqh[(size_t)HID * HID],      g_wql[(size_t)HID * HID];
__device__ __nv_bfloat16 g_wkh[(size_t)NKV * HD * HID], g_wkl[(size_t)NKV * HD * HID];
__device__ __nv_bfloat16 g_wvh[(size_t)NKV * HD * HID], g_wvl[(size_t)NKV * HD * HID];
__device__ __nv_bfloat16 g_woh[(size_t)HID * HID],      g_wol[(size_t)HID * HID];
__device__ float g_qf[(size_t)SEQ * NH * HD];
__device__ float g_kf[(size_t)SEQ * NKV * HD];
__device__ float g_vf[(size_t)SEQ * NKV * HD];
__device__ __nv_bfloat16 g_qh[(size_t)SEQ * NH * HD],   g_ql[(size_t)SEQ * NH * HD];
__device__ __nv_bfloat16 g_kh[(size_t)SEQ * NKV * HD],  g_kl[(size_t)SEQ * NKV * HD];
__device__ __nv_bfloat16 g_vth[(size_t)NKV * HD * SEQ], g_vtl[(size_t)NKV * HD * SEQ];
__device__ float g_sc[(size_t)NH * SEQ * SEQ];
__device__ __nv_bfloat16 g_ph[(size_t)NH * SEQ * SEQ],  g_pl[(size_t)NH * SEQ * SEQ];
__device__ __nv_bfloat16 g_ch[(size_t)SEQ * NH * HD],   g_cl[(size_t)SEQ * NH * HD];

// ---------------------------------------------------------------------------
// helpers
// ---------------------------------------------------------------------------
__device__ __forceinline__ void cpasync16(uint32_t s, const void* g) {
    asm volatile("cp.async.cg.shared.global [%0], [%1], 16;\n" :: "r"(s), "l"(g));
}
#define CPASYNC_COMMIT() asm volatile("cp.async.commit_group;\n" ::: "memory")
#define CPASYNC_WAIT0()  asm volatile("cp.async.wait_group 0;\n" ::: "memory")
#define CPASYNC_WAIT1()  asm volatile("cp.async.wait_group 1;\n" ::: "memory")

__device__ __forceinline__ void mma_bf16(float* c, const uint32_t* a, const uint32_t* b) {
    asm volatile(
        "mma.sync.aligned.m16n8k16.row.col.f32.bf16.bf16.f32 "
        "{%0,%1,%2,%3}, {%4,%5,%6,%7}, {%8,%9}, {%0,%1,%2,%3};"
        : "+f"(c[0]), "+f"(c[1]), "+f"(c[2]), "+f"(c[3])
        : "r"(a[0]), "r"(a[1]), "r"(a[2]), "r"(a[3]), "r"(b[0]), "r"(b[1]));
}

// ---------------------------------------------------------------------------
// bf16x3 tensor-core GEMM:  C[m,n] = sum_k A[m,k]*B[n,k]  (both K-major)
// A = Ah + Al, B = Bh + Bl; computes Ah*Bh + Ah*Bl + Al*Bh (fp32 accum).
// outMode 0: fp32 C.  outMode 1: bf16 hi/lo pair C.
// Tiles: 128x128 CTA, BK=32, 8 warps (2m x 4n), warp tile 64x32.
// smem rows padded to 80B -> fragment LDS.32 conflict-free.
// ---------------------------------------------------------------------------
#define BKG 32
#define ROW_B 80                         // bytes per smem row (64 data + 16 pad)
#define TILE_BYTES (128 * ROW_B)         // 10240
#define STAGE_BYTES (4 * TILE_BYTES)     // Ah, Al, Bh, Bl
#define GEMM_SMEM (2 * STAGE_BYTES)      // 81920 (double buffered)

__global__ __launch_bounds__(256)
void gemm_bf16x3(const __nv_bfloat16* __restrict__ Ah, const __nv_bfloat16* __restrict__ Al,
                 const __nv_bfloat16* __restrict__ Bh, const __nv_bfloat16* __restrict__ Bl,
                 float* __restrict__ Cf, __nv_bfloat16* __restrict__ Ch,
                 __nv_bfloat16* __restrict__ Cl,
                 int K, int lda, int ldb, int ldc,
                 long long sA, long long sB, long long sC, int bdiv,
                 int causalSkip, int causalKlim, int outMode)
{
    extern __shared__ char dsm[];

    const int bz = blockIdx.z;
    Ah += (long long)bz * sA;  Al += (long long)bz * sA;
    Bh += (long long)(bz / bdiv) * sB;  Bl += (long long)(bz / bdiv) * sB;
    if (outMode == 0) Cf += (long long)bz * sC;
    else { Ch += (long long)bz * sC; Cl += (long long)bz * sC; }

    const int m0 = blockIdx.y * 128;
    const int n0 = blockIdx.x * 128;
    if (causalSkip && n0 > m0) return;
    const int Keff  = causalKlim ? min(K, m0 + 128) : K;
    const int nIter = Keff / BKG;

    const uint32_t sbase = (uint32_t)__cvta_generic_to_shared(dsm);
    const int tid  = threadIdx.x;
    const int lane = tid & 31;
    const int wid  = tid >> 5;
    const int wm   = wid & 1;          // m offset wm*64
    const int wn   = wid >> 1;         // n offset wn*32
    const int lrow = lane >> 2;        // 0..7
    const int lk4  = (lane & 3) * 4;   // byte offset of k-pair

    float acc[4][4][4];
    #pragma unroll
    for (int i = 0; i < 4; i++)
        #pragma unroll
        for (int j = 0; j < 4; j++)
            #pragma unroll
            for (int r = 0; r < 4; r++) acc[i][j][r] = 0.0f;

    auto load_stage = [&](int buf, int k0) {
        const uint32_t tb = sbase + buf * STAGE_BYTES;
        #pragma unroll
        for (int t = 0; t < 2; t++) {
            const int idx = tid + t * 256;           // 0..511
            const int row = idx >> 2;                // 0..127
            const int c16 = idx & 3;                 // which 16B of the 64B row
            const uint32_t so = (uint32_t)(row * ROW_B + c16 * 16);
            const long long ka = (long long)(m0 + row) * lda + k0 + c16 * 8;
            const long long kb = (long long)(n0 + row) * ldb + k0 + c16 * 8;
            cpasync16(tb + so,                  Ah + ka);
            cpasync16(tb + TILE_BYTES + so,     Al + ka);
            cpasync16(tb + 2 * TILE_BYTES + so, Bh + kb);
            cpasync16(tb + 3 * TILE_BYTES + so, Bl + kb);
        }
        CPASYNC_COMMIT();
    };

    load_stage(0, 0);

    for (int c = 0; c < nIter; c++) {
        const int b = c & 1;
        if (c + 1 < nIter) { load_stage(b ^ 1, (c + 1) * BKG); CPASYNC_WAIT1(); }
        else               { CPASYNC_WAIT0(); }
        __syncthreads();

        const char* pAh = dsm + b * STAGE_BYTES;
        const char* pAl = pAh + TILE_BYTES;
        const char* pBh = pAh + 2 * TILE_BYTES;
        const char* pBl = pAh + 3 * TILE_BYTES;

        #pragma unroll
        for (int ks = 0; ks < 2; ks++) {
            const int kb0 = ks * 32 + lk4;       // byte offset within 64B row
            uint32_t afh[4][4], afl[4][4], bfh[4][2], bfl[4][2];
            #pragma unroll
            for (int mt = 0; mt < 4; mt++) {
                const int r0 = wm * 64 + mt * 16 + lrow;
                afh[mt][0] = *(const uint32_t*)(pAh + r0 * ROW_B + kb0);
                afh[mt][1] = *(const uint32_t*)(pAh + (r0 + 8) * ROW_B + kb0);
                afh[mt][2] = *(const uint32_t*)(pAh + r0 * ROW_B + kb0 + 16);
                afh[mt][3] = *(const uint32_t*)(pAh + (r0 + 8) * ROW_B + kb0 + 16);
                afl[mt][0] = *(const uint32_t*)(pAl + r0 * ROW_B + kb0);
                afl[mt][1] = *(const uint32_t*)(pAl + (r0 + 8) * ROW_B + kb0);
                afl[mt][2] = *(const uint32_t*)(pAl + r0 * ROW_B + kb0 + 16);
                afl[mt][3] = *(const uint32_t*)(pAl + (r0 + 8) * ROW_B + kb0 + 16);
            }
            #pragma unroll
            for (int nt = 0; nt < 4; nt++) {
                const int n = wn * 32 + nt * 8 + lrow;
                bfh[nt][0] = *(const uint32_t*)(pBh + n * ROW_B + kb0);
                bfh[nt][1] = *(const uint32_t*)(pBh + n * ROW_B + kb0 + 16);
                bfl[nt][0] = *(const uint32_t*)(pBl + n * ROW_B + kb0);
                bfl[nt][1] = *(const uint32_t*)(pBl + n * ROW_B + kb0 + 16);
            }
            #pragma unroll
            for (int mt = 0; mt < 4; mt++)
                #pragma unroll
                for (int nt = 0; nt < 4; nt++) {
                    mma_bf16(acc[mt][nt], afh[mt], bfh[nt]);
                    mma_bf16(acc[mt][nt], afh[mt], bfl[nt]);
                    mma_bf16(acc[mt][nt], afl[mt], bfh[nt]);
                }
        }
        __syncthreads();
    }

    // epilogue
    #pragma unroll
    for (int mt = 0; mt < 4; mt++) {
        const long long r = m0 + wm * 64 + mt * 16 + lrow;
        #pragma unroll
        for (int nt = 0; nt < 4; nt++) {
            const int cc = n0 + wn * 32 + nt * 8 + (lane & 3) * 2;
            if (outMode == 0) {
                *(float2*)(Cf + r * ldc + cc)       = make_float2(acc[mt][nt][0], acc[mt][nt][1]);
                *(float2*)(Cf + (r + 8) * ldc + cc) = make_float2(acc[mt][nt][2], acc[mt][nt][3]);
            } else {
                #pragma unroll
                for (int h = 0; h < 2; h++) {
                    #pragma unroll
                    for (int j = 0; j < 2; j++) {
                        const float v = acc[mt][nt][h * 2 + j];
                        const __nv_bfloat16 hi = __float2bfloat16(v);
                        const long long o = (r + h * 8) * ldc + cc + j;
                        Ch[o] = hi;
                        Cl[o] = __float2bfloat16(v - __bfloat162float(hi));
                    }
                }
            }
        }
    }
}

// ---------------------------------------------------------------------------
// fp32 -> (bf16 hi, bf16 lo) elementwise split, 4 elems/thread
// ---------------------------------------------------------------------------
__global__ void split_kernel(const float* __restrict__ s, __nv_bfloat16* __restrict__ h,
                             __nv_bfloat16* __restrict__ l, int n4)
{
    const int i = blockIdx.x * blockDim.x + threadIdx.x;
    if (i >= n4) return;
    const float4 v = ((const float4*)s)[i];
    __nv_bfloat16 h0 = __float2bfloat16(v.x), h1 = __float2bfloat16(v.y);
    __nv_bfloat16 h2 = __float2bfloat16(v.z), h3 = __float2bfloat16(v.w);
    h[i * 4 + 0] = h0; h[i * 4 + 1] = h1; h[i * 4 + 2] = h2; h[i * 4 + 3] = h3;
    l[i * 4 + 0] = __float2bfloat16(v.x - __bfloat162float(h0));
    l[i * 4 + 1] = __float2bfloat16(v.y - __bfloat162float(h1));
    l[i * 4 + 2] = __float2bfloat16(v.z - __bfloat162float(h2));
    l[i * 4 + 3] = __float2bfloat16(v.w - __bfloat162float(h3));
}

// ---------------------------------------------------------------------------
// RoPE (rotate-half) + split:  fp32 [S, heads, 128] -> bf16 hi/lo
// ---------------------------------------------------------------------------
__global__ void rope_split_kernel(const float* __restrict__ t,
                                  const float* __restrict__ cosT,
                                  const float* __restrict__ sinT,
                                  __nv_bfloat16* __restrict__ oh,
                                  __nv_bfloat16* __restrict__ ol, int heads)
{
    const int idx = blockIdx.x * blockDim.x + threadIdx.x;
    const int total = SEQ * heads * (HD / 2);
    if (idx >= total) return;
    const int d = idx % (HD / 2);
    const int h = (idx / (HD / 2)) % heads;
    const int s = idx / ((HD / 2) * heads);

    const float c1 = cosT[s * HD + d];
    const float s1 = sinT[s * HD + d];
    const float c2 = cosT[s * HD + d + HD / 2];
    const float s2 = sinT[s * HD + d + HD / 2];

    const float* row = t + (long long)s * heads * HD + h * HD;
    const float x1 = row[d];
    const float x2 = row[d + HD / 2];
    const float y1 = x1 * c1 - x2 * s1;
    const float y2 = x2 * c2 + x1 * s2;

    const long long base = (long long)s * heads * HD + h * HD;
    const __nv_bfloat16 h1 = __float2bfloat16(y1);
    const __nv_bfloat16 h2 = __float2bfloat16(y2);
    oh[base + d]          = h1;
    ol[base + d]          = __float2bfloat16(y1 - __bfloat162float(h1));
    oh[base + d + HD / 2] = h2;
    ol[base + d + HD / 2] = __float2bfloat16(y2 - __bfloat162float(h2));
}

// ---------------------------------------------------------------------------
// V transpose + split:  v fp32 [S, NKV, 128] -> vt bf16 hi/lo [NKV, 128, S]
// ---------------------------------------------------------------------------
__global__ void vtsplit_kernel(const float* __restrict__ v,
                               __nv_bfloat16* __restrict__ th,
                               __nv_bfloat16* __restrict__ tl)
{
    __shared__ float tile[32][33];
    const int h = blockIdx.z;
    const int s0 = blockIdx.x * 32;
    const int d0 = blockIdx.y * 32;
    const int tx = threadIdx.x, ty = threadIdx.y;

    #pragma unroll
    for (int j = 0; j < 4; j++) {
        const int s = s0 + ty + 8 * j;
        tile[ty + 8 * j][tx] = v[(long long)s * (NKV * HD) + h * HD + d0 + tx];
    }
    __syncthreads();
    #pragma unroll
    for (int j = 0; j < 4; j++) {
        const int d = d0 + ty + 8 * j;
        const int s = s0 + tx;
        const float val = tile[tx][ty + 8 * j];
        const __nv_bfloat16 hi = __float2bfloat16(val);
        const long long o = ((long long)h * HD + d) * SEQ + s;
        th[o] = hi;
        tl[o] = __float2bfloat16(val - __bfloat162float(hi));
    }
}

// ---------------------------------------------------------------------------
// Causal softmax: reads fp32 scores, writes P as bf16 hi/lo;
// zero-fills (q, tile_end) so the context GEMM's K-clamp is exact.
// ---------------------------------------------------------------------------
__global__ __launch_bounds__(256)
void softmax_kernel(float* __restrict__ scores,
                    __nv_bfloat16* __restrict__ Ph, __nv_bfloat16* __restrict__ Pl)
{
    const int q = blockIdx.x;
    const int h = blockIdx.y;
    const long long roff = ((long long)h * SEQ + q) * SEQ;
    float* row = scores + roff;
    __nv_bfloat16* ph = Ph + roff;
    __nv_bfloat16* pl = Pl + roff;
    const int tid = threadIdx.x;
    const float scale = 0.08838834764831845f;   // 1/sqrt(128)
    const int n = q + 1;
    const int mend = ((q >> 7) + 1) << 7;       // zero-fill to 128-tile boundary

    __shared__ float red[256];

    float mx = -INFINITY;
    for (int k = tid; k < n; k += 256) mx = fmaxf(mx, row[k] * scale);
    red[tid] = mx;
    __syncthreads();
    for (int st = 128; st > 0; st >>= 1) {
        if (tid < st) red[tid] = fmaxf(red[tid], red[tid + st]);
        __syncthreads();
    }
    mx = red[0];
    __syncthreads();

    float sum = 0.0f;
    for (int k = tid; k < n; k += 256) {
        const float e = __expf(row[k] * scale - mx);
        row[k] = e;
        sum += e;
    }
    red[tid] = sum;
    __syncthreads();
    for (int st = 128; st > 0; st >>= 1) {
        if (tid < st) red[tid] += red[tid + st];
        __syncthreads();
    }
    const float inv = 1.0f / red[0];
    __syncthreads();

    for (int k = tid; k < n; k += 256) {
        const float p = row[k] * inv;
        const __nv_bfloat16 hi = __float2bfloat16(p);
        ph[k] = hi;
        pl[k] = __float2bfloat16(p - __bfloat162float(hi));
    }
    const __nv_bfloat16 z = __float2bfloat16(0.0f);
    for (int k = n + tid; k < mend; k += 256) { ph[k] = z; pl[k] = z; }
}

// ---------------------------------------------------------------------------
extern "C" void kernel_launch(void* const* d_in, const int* in_sizes, int n_in,
                              void* d_out, int out_size)
{
    const float* x    = (const float*)d_in[0];
    const float* Wq   = (const float*)d_in[1];
    const float* Wk   = (const float*)d_in[2];
    const float* Wv   = (const float*)d_in[3];
    const float* Wo   = (const float*)d_in[4];
    const float* cosT = (const float*)d_in[5];
    const float* sinT = (const float*)d_in[6];
    float* out = (float*)d_out;

    cudaFuncSetAttribute(gemm_bf16x3, cudaFuncAttributeMaxDynamicSharedMemorySize, GEMM_SMEM);

    const dim3 b256(256);

    // --- split inputs/weights to bf16 hi/lo ---
    {
        const int n4a = SEQ * HID / 4;         // x, Wq, Wo
        const int n4b = NKV * HD * HID / 4;    // Wk, Wv
        split_kernel<<<(n4a + 255) / 256, b256>>>(x,  g_xh,  g_xl,  n4a);
        split_kernel<<<(n4a + 255) / 256, b256>>>(Wq, g_wqh, g_wql, n4a);
        split_kernel<<<(n4b + 255) / 256, b256>>>(Wk, g_wkh, g_wkl, n4b);
        split_kernel<<<(n4b + 255) / 256, b256>>>(Wv, g_wvh, g_wvl, n4b);
        split_kernel<<<(n4a + 255) / 256, b256>>>(Wo, g_woh, g_wol, n4a);
    }

    // --- QKV projections (NT): C[m,n] = x[m,:] . W[n,:] ---
    gemm_bf16x3<<<dim3(16, 16, 1), b256, GEMM_SMEM>>>(
        g_xh, g_xl, g_wqh, g_wql, g_qf, nullptr, nullptr,
        HID, HID, HID, NH * HD, 0, 0, 0, 1, 0, 0, 0);
    gemm_bf16x3<<<dim3(8, 16, 1), b256, GEMM_SMEM>>>(
        g_xh, g_xl, g_wkh, g_wkl, g_kf, nullptr, nullptr,
        HID, HID, HID, NKV * HD, 0, 0, 0, 1, 0, 0, 0);
    gemm_bf16x3<<<dim3(8, 16, 1), b256, GEMM_SMEM>>>(
        g_xh, g_xl, g_wvh, g_wvl, g_vf, nullptr, nullptr,
        HID, HID, HID, NKV * HD, 0, 0, 0, 1, 0, 0, 0);

    // --- RoPE + split q/k; transpose + split v ---
    {
        const int tq = SEQ * NH * (HD / 2);
        rope_split_kernel<<<(tq + 255) / 256, b256>>>(g_qf, cosT, sinT, g_qh, g_ql, NH);
        const int tk = SEQ * NKV * (HD / 2);
        rope_split_kernel<<<(tk + 255) / 256, b256>>>(g_kf, cosT, sinT, g_kh, g_kl, NKV);
        vtsplit_kernel<<<dim3(SEQ / 32, HD / 32, NKV), dim3(32, 8)>>>(g_vf, g_vth, g_vtl);
    }

    // --- scores[h] = Q_h . K_{h/2}^T  (causal tile skip) ---
    gemm_bf16x3<<<dim3(16, 16, NH), b256, GEMM_SMEM>>>(
        g_qh, g_ql, g_kh, g_kl, g_sc, nullptr, nullptr,
        HD, NH * HD, NKV * HD, SEQ,
        HD, HD, (long long)SEQ * SEQ, 2, 1, 0, 0);

    // --- causal softmax -> P hi/lo ---
    softmax_kernel<<<dim3(SEQ, NH), b256>>>(g_sc, g_ph, g_pl);

    // --- ctx[h] = P_h . V_{h/2}  (B = V^T, K-clamped); writes bf16 hi/lo ---
    gemm_bf16x3<<<dim3(1, 16, NH), b256, GEMM_SMEM>>>(
        g_ph, g_pl, g_vth, g_vtl, nullptr, g_ch, g_cl,
        SEQ, SEQ, SEQ, NH * HD,
        (long long)SEQ * SEQ, (long long)HD * SEQ, HD, 2, 0, 1, 1);

    // --- out = ctx . Wo^T ---
    gemm_bf16x3<<<dim3(16, 16, 1), b256, GEMM_SMEM>>>(
        g_ch, g_cl, g_woh, g_wol, out, nullptr, nullptr,
        NH * HD, NH * HD, NH * HD, HID, 0, 0, 0, 1, 0, 0, 0);
}

// round 9
// speedup vs baseline: 3.0559x; 3.0559x over previous
#include <cuda_runtime.h>
#include <math.h>
#include <stdint.h>

#define SEQ 2048
#define HID 2048
#define NH  16
#define NKV 8
#define HD  128

typedef unsigned long long ull;

// Scratch (allocation-free: __device__ globals)
__device__ float g_q[(size_t)SEQ * NH * HD];
__device__ float g_k[(size_t)SEQ * NKV * HD];
__device__ float g_v[(size_t)SEQ * NKV * HD];
__device__ float g_scores[(size_t)NH * SEQ * SEQ];
__device__ float g_ctx[(size_t)SEQ * NH * HD];

// ---------------------------------------------------------------------------
// packed f32x2 helpers (Blackwell sm_100+; PTX ISA 8.6)
// ---------------------------------------------------------------------------
__device__ __forceinline__ void ffma2(ull& acc, ull a, ull b) {
    asm("fma.rn.f32x2 %0, %1, %2, %0;" : "+l"(acc) : "l"(a), "l"(b));
}
__device__ __forceinline__ ull dup2(float v) {
    ull r;
    asm("mov.b64 %0, {%1, %1};" : "=l"(r) : "f"(v));
    return r;
}
__device__ __forceinline__ float2 unpack2(ull v) {
    float2 f;
    asm("mov.b64 {%0, %1}, %2;" : "=f"(f.x), "=f"(f.y) : "l"(v));
    return f;
}

// ---------------------------------------------------------------------------
// Batched fp32 GEMM on packed FFMA2.
//   NT (TB_NT=true):  C[m,n] = sum_k A[m,k] * B[n,k]
//   NN (TB_NT=false): C[m,n] = sum_k A[m,k] * B[k,n]
// Batch offsets: A += bz*sA, B += (bz/bdiv)*sB, C += bz*sC.
// causalSkip: skip tiles fully above the diagonal. causalKlim: clamp K to m0+128.
// M,N multiples of 128; K multiple of 16.
//
// smem: As_dup[16][256] (each A value stored twice -> (a,a) pairs),
//       Bs[16][132]     (k-major rows of n values; pairs along n).
// Thread (tx,ty), 16x16: m-blocks {ty*4, 64+ty*4}, n-blocks {tx*4, 64+tx*4}.
// Per kk: 4x LDS.128 (A dup pairs) + 2x LDS.128 (B pairs) + 32 FFMA2.
// ---------------------------------------------------------------------------
#define BKG 16
#define ADUP_W 256                        // floats per As_dup row
#define BS_W   132                        // floats per Bs row
#define STAGE_F (BKG * ADUP_W + BKG * BS_W)   // floats per stage = 6208
#define GEMM_SMEM (2 * STAGE_F * 4)           // 49664 bytes

template <bool TB_NT>
__global__ __launch_bounds__(256, 2)
void gemm_f32x2(const float* __restrict__ A, const float* __restrict__ B,
                float* __restrict__ C,
                int M, int N, int K, int lda, int ldb, int ldc,
                long long sA, long long sB, long long sC, int bdiv,
                int causalSkip, int causalKlim)
{
    extern __shared__ float smf[];

    const int bz = blockIdx.z;
    A += (long long)bz * sA;
    B += (long long)(bz / bdiv) * sB;
    C += (long long)bz * sC;

    const int m0 = blockIdx.y * 128;
    const int n0 = blockIdx.x * 128;
    if (causalSkip && n0 > m0) return;
    const int Keff  = causalKlim ? min(K, m0 + 128) : K;
    const int nIter = Keff / BKG;

    const int tid = threadIdx.x;
    const int tx  = tid & 15;
    const int ty  = tid >> 4;

    // global-load assignment
    const int gr = tid >> 1;            // 0..127 (A row / NT-B row)
    const int gk = (tid & 1) * 8;       // k offset (two float4s: gk, gk+4)
    const int bkr = tid >> 4;           // NN-B: k row 0..15
    const int bn4 = (tid & 15) * 8;     // NN-B: n offset (two float4s)

    ull acc[8][4];
    #pragma unroll
    for (int i = 0; i < 8; i++)
        #pragma unroll
        for (int j = 0; j < 4; j++) acc[i][j] = 0ull;

    float4 aR0, aR1, bR0, bR1;

    auto ldg_stage = [&](int k0) {
        const float* ap = A + (long long)(m0 + gr) * lda + k0 + gk;
        aR0 = *(const float4*)ap;
        aR1 = *(const float4*)(ap + 4);
        if (TB_NT) {
            const float* bp = B + (long long)(n0 + gr) * ldb + k0 + gk;
            bR0 = *(const float4*)bp;
            bR1 = *(const float4*)(bp + 4);
        } else {
            const float* bp = B + (long long)(k0 + bkr) * ldb + n0 + bn4;
            bR0 = *(const float4*)bp;
            bR1 = *(const float4*)(bp + 4);
        }
    };

    auto sts_stage = [&](int buf) {
        float* sA_ = smf + buf * STAGE_F;
        float* sB_ = sA_ + BKG * ADUP_W;
        // A: duplicate each value -> (a,a) pair at As_dup[k][2m]
        ull* sAd = (ull*)sA_;
        sAd[(gk + 0) * 128 + gr] = dup2(aR0.x);
        sAd[(gk + 1) * 128 + gr] = dup2(aR0.y);
        sAd[(gk + 2) * 128 + gr] = dup2(aR0.z);
        sAd[(gk + 3) * 128 + gr] = dup2(aR0.w);
        sAd[(gk + 4) * 128 + gr] = dup2(aR1.x);
        sAd[(gk + 5) * 128 + gr] = dup2(aR1.y);
        sAd[(gk + 6) * 128 + gr] = dup2(aR1.z);
        sAd[(gk + 7) * 128 + gr] = dup2(aR1.w);
        if (TB_NT) {
            // transpose: Bs[k][n] = B[n][k]
            sB_[(gk + 0) * BS_W + gr] = bR0.x;
            sB_[(gk + 1) * BS_W + gr] = bR0.y;
            sB_[(gk + 2) * BS_W + gr] = bR0.z;
            sB_[(gk + 3) * BS_W + gr] = bR0.w;
            sB_[(gk + 4) * BS_W + gr] = bR1.x;
            sB_[(gk + 5) * BS_W + gr] = bR1.y;
            sB_[(gk + 6) * BS_W + gr] = bR1.z;
            sB_[(gk + 7) * BS_W + gr] = bR1.w;
        } else {
            *(float4*)(sB_ + bkr * BS_W + bn4)     = bR0;
            *(float4*)(sB_ + bkr * BS_W + bn4 + 4) = bR1;
        }
    };

    ldg_stage(0);
    sts_stage(0);
    __syncthreads();

    int buf = 0;
    for (int it = 0; it < nIter; it++) {
        const bool hasNext = (it + 1) < nIter;
        if (hasNext) ldg_stage((it + 1) * BKG);

        const ull*   Ad = (const ull*)(smf + buf * STAGE_F);
        const float* Bf = smf + buf * STAGE_F + BKG * ADUP_W;

        #pragma unroll
        for (int kk = 0; kk < BKG; kk++) {
            const ull* arow = Ad + kk * 128;
            const ull* brow = (const ull*)(Bf + kk * BS_W);
            ull aP[8], bP[4];
            #pragma unroll
            for (int i = 0; i < 4; i++) aP[i]     = arow[ty * 4 + i];
            #pragma unroll
            for (int i = 0; i < 4; i++) aP[4 + i] = arow[64 + ty * 4 + i];
            bP[0] = brow[tx * 2];
            bP[1] = brow[tx * 2 + 1];
            bP[2] = brow[32 + tx * 2];
            bP[3] = brow[32 + tx * 2 + 1];
            #pragma unroll
            for (int mi = 0; mi < 8; mi++)
                #pragma unroll
                for (int np = 0; np < 4; np++)
                    ffma2(acc[mi][np], aP[mi], bP[np]);
        }

        if (hasNext) sts_stage(buf ^ 1);
        __syncthreads();
        buf ^= 1;
    }

    // epilogue
    #pragma unroll
    for (int mi = 0; mi < 8; mi++) {
        const int m = (mi < 4) ? (ty * 4 + mi) : (64 + ty * 4 + mi - 4);
        float* crow = C + (long long)(m0 + m) * ldc + n0;
        const float2 p0 = unpack2(acc[mi][0]);
        const float2 p1 = unpack2(acc[mi][1]);
        const float2 p2 = unpack2(acc[mi][2]);
        const float2 p3 = unpack2(acc[mi][3]);
        *(float4*)(crow + tx * 4)      = make_float4(p0.x, p0.y, p1.x, p1.y);
        *(float4*)(crow + 64 + tx * 4) = make_float4(p2.x, p2.y, p3.x, p3.y);
    }
}

// ---------------------------------------------------------------------------
// RoPE (rotate-half, non-interleaved), in-place on [S, heads, 128]
// ---------------------------------------------------------------------------
__global__ void rope_kernel(float* __restrict__ t,
                            const float* __restrict__ cosT,
                            const float* __restrict__ sinT, int heads)
{
    const int idx = blockIdx.x * blockDim.x + threadIdx.x;
    const int total = SEQ * heads * (HD / 2);
    if (idx >= total) return;
    const int d = idx % (HD / 2);
    const int h = (idx / (HD / 2)) % heads;
    const int s = idx / ((HD / 2) * heads);

    const float c1 = cosT[s * HD + d];
    const float s1 = sinT[s * HD + d];
    const float c2 = cosT[s * HD + d + HD / 2];
    const float s2 = sinT[s * HD + d + HD / 2];

    float* row = t + (long long)s * heads * HD + h * HD;
    const float x1 = row[d];
    const float x2 = row[d + HD / 2];
    row[d]          = x1 * c1 - x2 * s1;
    row[d + HD / 2] = x2 * c2 + x1 * s2;
}

// ---------------------------------------------------------------------------
// Causal softmax (applies 1/sqrt(D)); zero-fills masked tail up to the
// 128-tile boundary so the context GEMM's K-clamp is exact.
// ---------------------------------------------------------------------------
__global__ __launch_bounds__(256)
void softmax_kernel(float* __restrict__ scores)
{
    const int q = blockIdx.x;
    const int h = blockIdx.y;
    float* row = scores + ((size_t)h * SEQ + q) * SEQ;
    const int tid = threadIdx.x;
    const float scale = 0.08838834764831845f;   // 1/sqrt(128)
    const int n = q + 1;
    const int mend = ((q >> 7) + 1) << 7;

    __shared__ float red[256];

    float mx = -INFINITY;
    for (int k = tid; k < n; k += 256) mx = fmaxf(mx, row[k] * scale);
    red[tid] = mx;
    __syncthreads();
    for (int st = 128; st > 0; st >>= 1) {
        if (tid < st) red[tid] = fmaxf(red[tid], red[tid + st]);
        __syncthreads();
    }
    mx = red[0];
    __syncthreads();

    float sum = 0.0f;
    for (int k = tid; k < n; k += 256) {
        const float e = __expf(row[k] * scale - mx);
        row[k] = e;
        sum += e;
    }
    red[tid] = sum;
    __syncthreads();
    for (int st = 128; st > 0; st >>= 1) {
        if (tid < st) red[tid] += red[tid + st];
        __syncthreads();
    }
    const float inv = 1.0f / red[0];
    __syncthreads();

    for (int k = tid; k < n; k += 256) row[k] *= inv;
    for (int k = n + tid; k < mend; k += 256) row[k] = 0.0f;
}

// ---------------------------------------------------------------------------
extern "C" void kernel_launch(void* const* d_in, const int* in_sizes, int n_in,
                              void* d_out, int out_size)
{
    const float* x    = (const float*)d_in[0];
    const float* Wq   = (const float*)d_in[1];
    const float* Wk   = (const float*)d_in[2];
    const float* Wv   = (const float*)d_in[3];
    const float* Wo   = (const float*)d_in[4];
    const float* cosT = (const float*)d_in[5];
    const float* sinT = (const float*)d_in[6];
    float* out = (float*)d_out;

    float* q   = g_q;
    float* k   = g_k;
    float* v   = g_v;
    float* sc  = g_scores;
    float* ctx = g_ctx;

    cudaFuncSetAttribute(gemm_f32x2<true>,  cudaFuncAttributeMaxDynamicSharedMemorySize, GEMM_SMEM);
    cudaFuncSetAttribute(gemm_f32x2<false>, cudaFuncAttributeMaxDynamicSharedMemorySize, GEMM_SMEM);

    const dim3 blk(256);

    // QKV projections (NT)
    gemm_f32x2<true><<<dim3(16, 16, 1), blk, GEMM_SMEM>>>(
        x, Wq, q, SEQ, 2048, HID, HID, HID, 2048, 0, 0, 0, 1, 0, 0);
    gemm_f32x2<true><<<dim3(8, 16, 1), blk, GEMM_SMEM>>>(
        x, Wk, k, SEQ, 1024, HID, HID, HID, 1024, 0, 0, 0, 1, 0, 0);
    gemm_f32x2<true><<<dim3(8, 16, 1), blk, GEMM_SMEM>>>(
        x, Wv, v, SEQ, 1024, HID, HID, HID, 1024, 0, 0, 0, 1, 0, 0);

    // RoPE on Q (16 heads) and K (8 heads)
    {
        const int tq = SEQ * NH * (HD / 2);
        rope_kernel<<<(tq + 255) / 256, blk>>>(q, cosT, sinT, NH);
        const int tk = SEQ * NKV * (HD / 2);
        rope_kernel<<<(tk + 255) / 256, blk>>>(k, cosT, sinT, NKV);
    }

    // scores[h] = Q_h @ K_{h/2}^T  (NT, causal tile skip)
    gemm_f32x2<true><<<dim3(16, 16, NH), blk, GEMM_SMEM>>>(
        q, k, sc, SEQ, SEQ, HD, NH * HD, NKV * HD, SEQ,
        HD, HD, (long long)SEQ * SEQ, 2, 1, 0);

    // causal softmax (scale + zero-fill to tile boundary)
    softmax_kernel<<<dim3(SEQ, NH), blk>>>(sc);

    // ctx[h] = P_h @ V_{h/2}  (NN, K clamped by causality)
    gemm_f32x2<false><<<dim3(1, 16, NH), blk, GEMM_SMEM>>>(
        sc, v, ctx, SEQ, HD, SEQ, SEQ, NKV * HD, NH * HD,
        (long long)SEQ * SEQ, HD, HD, 2, 0, 1);

    // out = ctx @ Wo^T  (NT)
    gemm_f32x2<true><<<dim3(16, 16, 1), blk, GEMM_SMEM>>>(
        ctx, Wo, out, SEQ, HID, NH * HD, NH * HD, NH * HD, HID, 0, 0, 0, 1, 0, 0);
}

// round 11
// speedup vs baseline: 3.1193x; 1.0208x over previous
#include <cuda_runtime.h>
#include <math.h>
#include <stdint.h>

#define SEQ 2048
#define HID 2048
#define NH  16
#define NKV 8
#define HD  128

typedef unsigned long long ull;

// Scratch (allocation-free: __device__ globals)
__device__ float g_q[(size_t)SEQ * NH * HD];
__device__ float g_k[(size_t)SEQ * NKV * HD];
__device__ float g_v[(size_t)SEQ * NKV * HD];
__device__ float g_ctx[(size_t)SEQ * NH * HD];

// ---------------------------------------------------------------------------
// packed f32x2 helpers
// ---------------------------------------------------------------------------
__device__ __forceinline__ void ffma2(ull& acc, ull a, ull b) {
    asm("fma.rn.f32x2 %0, %1, %2, %0;" : "+l"(acc) : "l"(a), "l"(b));
}
__device__ __forceinline__ ull dup2(float v) {
    ull r;
    asm("mov.b64 %0, {%1, %1};" : "=l"(r) : "f"(v));
    return r;
}
__device__ __forceinline__ float2 unpack2(ull v) {
    float2 f;
    asm("mov.b64 {%0, %1}, %2;" : "=f"(f.x), "=f"(f.y) : "l"(v));
    return f;
}
__device__ __forceinline__ void cpasync16(uint32_t s, const void* g) {
    asm volatile("cp.async.cg.shared.global [%0], [%1], 16;\n" :: "r"(s), "l"(g));
}
#define CPASYNC_COMMIT() asm volatile("cp.async.commit_group;\n" ::: "memory")
#define CPASYNC_WAIT0()  asm volatile("cp.async.wait_group 0;\n" ::: "memory")
#define CPASYNC_WAIT1()  asm volatile("cp.async.wait_group 1;\n" ::: "memory")

// ---------------------------------------------------------------------------
// Proven R9 batched fp32 GEMM on packed FFMA2 (NT / NN).
// ---------------------------------------------------------------------------
#define BKG 16
#define ADUP_W 256
#define BS_W   132
#define STAGE_F (BKG * ADUP_W + BKG * BS_W)
#define GEMM_SMEM (2 * STAGE_F * 4)

template <bool TB_NT>
__global__ __launch_bounds__(256, 2)
void gemm_f32x2(const float* __restrict__ A, const float* __restrict__ B,
                float* __restrict__ C,
                int M, int N, int K, int lda, int ldb, int ldc,
                long long sA, long long sB, long long sC, int bdiv,
                int causalSkip, int causalKlim)
{
    extern __shared__ float smf[];

    const int bz = blockIdx.z;
    A += (long long)bz * sA;
    B += (long long)(bz / bdiv) * sB;
    C += (long long)bz * sC;

    const int m0 = blockIdx.y * 128;
    const int n0 = blockIdx.x * 128;
    if (causalSkip && n0 > m0) return;
    const int Keff  = causalKlim ? min(K, m0 + 128) : K;
    const int nIter = Keff / BKG;

    const int tid = threadIdx.x;
    const int tx  = tid & 15;
    const int ty  = tid >> 4;
    const int gr  = tid >> 1;
    const int gk  = (tid & 1) * 8;
    const int bkr = tid >> 4;
    const int bn4 = (tid & 15) * 8;

    ull acc[8][4];
    #pragma unroll
    for (int i = 0; i < 8; i++)
        #pragma unroll
        for (int j = 0; j < 4; j++) acc[i][j] = 0ull;

    float4 aR0, aR1, bR0, bR1;

    auto ldg_stage = [&](int k0) {
        const float* ap = A + (long long)(m0 + gr) * lda + k0 + gk;
        aR0 = *(const float4*)ap;
        aR1 = *(const float4*)(ap + 4);
        if (TB_NT) {
            const float* bp = B + (long long)(n0 + gr) * ldb + k0 + gk;
            bR0 = *(const float4*)bp;
            bR1 = *(const float4*)(bp + 4);
        } else {
            const float* bp = B + (long long)(k0 + bkr) * ldb + n0 + bn4;
            bR0 = *(const float4*)bp;
            bR1 = *(const float4*)(bp + 4);
        }
    };

    auto sts_stage = [&](int buf) {
        float* sA_ = smf + buf * STAGE_F;
        float* sB_ = sA_ + BKG * ADUP_W;
        ull* sAd = (ull*)sA_;
        sAd[(gk + 0) * 128 + gr] = dup2(aR0.x);
        sAd[(gk + 1) * 128 + gr] = dup2(aR0.y);
        sAd[(gk + 2) * 128 + gr] = dup2(aR0.z);
        sAd[(gk + 3) * 128 + gr] = dup2(aR0.w);
        sAd[(gk + 4) * 128 + gr] = dup2(aR1.x);
        sAd[(gk + 5) * 128 + gr] = dup2(aR1.y);
        sAd[(gk + 6) * 128 + gr] = dup2(aR1.z);
        sAd[(gk + 7) * 128 + gr] = dup2(aR1.w);
        if (TB_NT) {
            sB_[(gk + 0) * BS_W + gr] = bR0.x;
            sB_[(gk + 1) * BS_W + gr] = bR0.y;
            sB_[(gk + 2) * BS_W + gr] = bR0.z;
            sB_[(gk + 3) * BS_W + gr] = bR0.w;
            sB_[(gk + 4) * BS_W + gr] = bR1.x;
            sB_[(gk + 5) * BS_W + gr] = bR1.y;
            sB_[(gk + 6) * BS_W + gr] = bR1.z;
            sB_[(gk + 7) * BS_W + gr] = bR1.w;
        } else {
            *(float4*)(sB_ + bkr * BS_W + bn4)     = bR0;
            *(float4*)(sB_ + bkr * BS_W + bn4 + 4) = bR1;
        }
    };

    ldg_stage(0);
    sts_stage(0);
    __syncthreads();

    int buf = 0;
    for (int it = 0; it < nIter; it++) {
        const bool hasNext = (it + 1) < nIter;
        if (hasNext) ldg_stage((it + 1) * BKG);

        const ull*   Ad = (const ull*)(smf + buf * STAGE_F);
        const float* Bf = smf + buf * STAGE_F + BKG * ADUP_W;

        #pragma unroll
        for (int kk = 0; kk < BKG; kk++) {
            const ull* arow = Ad + kk * 128;
            const ull* brow = (const ull*)(Bf + kk * BS_W);
            ull aP[8], bP[4];
            #pragma unroll
            for (int i = 0; i < 4; i++) aP[i]     = arow[ty * 4 + i];
            #pragma unroll
            for (int i = 0; i < 4; i++) aP[4 + i] = arow[64 + ty * 4 + i];
            bP[0] = brow[tx * 2];
            bP[1] = brow[tx * 2 + 1];
            bP[2] = brow[32 + tx * 2];
            bP[3] = brow[32 + tx * 2 + 1];
            #pragma unroll
            for (int mi = 0; mi < 8; mi++)
                #pragma unroll
                for (int np = 0; np < 4; np++)
                    ffma2(acc[mi][np], aP[mi], bP[np]);
        }

        if (hasNext) sts_stage(buf ^ 1);
        __syncthreads();
        buf ^= 1;
    }

    #pragma unroll
    for (int mi = 0; mi < 8; mi++) {
        const int m = (mi < 4) ? (ty * 4 + mi) : (64 + ty * 4 + mi - 4);
        float* crow = C + (long long)(m0 + m) * ldc + n0;
        const float2 p0 = unpack2(acc[mi][0]);
        const float2 p1 = unpack2(acc[mi][1]);
        const float2 p2 = unpack2(acc[mi][2]);
        const float2 p3 = unpack2(acc[mi][3]);
        *(float4*)(crow + tx * 4)      = make_float4(p0.x, p0.y, p1.x, p1.y);
        *(float4*)(crow + 64 + tx * 4) = make_float4(p2.x, p2.y, p3.x, p3.y);
    }
}

// ---------------------------------------------------------------------------
// RoPE (rotate-half, non-interleaved), in-place on [S, heads, 128] (R9 proven)
// ---------------------------------------------------------------------------
__global__ void rope_kernel(float* __restrict__ t,
                            const float* __restrict__ cosT,
                            const float* __restrict__ sinT, int heads)
{
    const int idx = blockIdx.x * blockDim.x + threadIdx.x;
    const int total = SEQ * heads * (HD / 2);
    if (idx >= total) return;
    const int d = idx % (HD / 2);
    const int h = (idx / (HD / 2)) % heads;
    const int s = idx / ((HD / 2) * heads);

    const float c1 = cosT[s * HD + d];
    const float s1 = sinT[s * HD + d];
    const float c2 = cosT[s * HD + d + HD / 2];
    const float s2 = sinT[s * HD + d + HD / 2];

    float* row = t + (long long)s * heads * HD + h * HD;
    const float x1 = row[d];
    const float x2 = row[d + HD / 2];
    row[d]          = x1 * c1 - x2 * s1;
    row[d + HD / 2] = x2 * c2 + x1 * s2;
}

// ---------------------------------------------------------------------------
// Flash attention: per CTA one (head, 64 q-rows). Online softmax, exact causal
// mask, 64-row K/V tiles double-buffered via cp.async. Applies 1/sqrt(128) to
// Q at smem load time.
// ---------------------------------------------------------------------------
#define BQ 64
#define BKT 64
#define KVSTR 132
#define QTSTR 68
#define SSTR 68
#define OFF_QT 0
#define OFF_K  (OFF_QT + 128 * QTSTR)
#define OFF_V  (OFF_K + 2 * BKT * KVSTR)
#define OFF_S  (OFF_V + 2 * BKT * KVSTR)
#define OFF_M  (OFF_S + BQ * SSTR)
#define OFF_L  (OFF_M + 64)
#define OFF_AL (OFF_L + 64)
#define FA_SMEM ((OFF_AL + 64) * 4)

__global__ __launch_bounds__(256, 1)
void flash_kernel(const float* __restrict__ q, const float* __restrict__ k,
                  const float* __restrict__ v, float* __restrict__ ctx)
{
    extern __shared__ float fs[];
    float* sQT = fs + OFF_QT;
    float* sS  = fs + OFF_S;
    float* sM  = fs + OFF_M;
    float* sL  = fs + OFF_L;
    float* sAl = fs + OFF_AL;

    const int qt = (int)gridDim.x - 1 - (int)blockIdx.x;  // long CTAs first
    const int h  = blockIdx.y;
    const int q0 = qt * BQ;
    const int tid = threadIdx.x;
    const int nt = qt + 1;
    const float qscale = 0.08838834764831845f;   // 1/sqrt(128)

    const uint32_t sbase = (uint32_t)__cvta_generic_to_shared(fs);

    // load Q tile (scaled), transpose into sQT[d][q]
    {
        const int r = tid >> 2, seg = tid & 3;
        const float* gp = q + (size_t)(q0 + r) * (NH * HD) + h * HD + seg * 32;
        #pragma unroll
        for (int i = 0; i < 8; i++) {
            const float4 f4 = ((const float4*)gp)[i];
            const int d = seg * 32 + i * 4;
            sQT[(d + 0) * QTSTR + r] = f4.x * qscale;
            sQT[(d + 1) * QTSTR + r] = f4.y * qscale;
            sQT[(d + 2) * QTSTR + r] = f4.z * qscale;
            sQT[(d + 3) * QTSTR + r] = f4.w * qscale;
        }
    }
    if (tid < 64) { sM[tid] = -INFINITY; sL[tid] = 0.0f; }

    const int lr = tid >> 2, lseg = tid & 3;
    const float* kbase = k + (size_t)lr * (NKV * HD) + (h >> 1) * HD + lseg * 32;
    const float* vbase = v + (size_t)lr * (NKV * HD) + (h >> 1) * HD + lseg * 32;
    auto loadKV = [&](int buf, int t) {
        const size_t goff = (size_t)t * BKT * (NKV * HD);
        const uint32_t sk = sbase + (uint32_t)(OFF_K + buf * BKT * KVSTR + lr * KVSTR + lseg * 32) * 4;
        const uint32_t sv = sbase + (uint32_t)(OFF_V + buf * BKT * KVSTR + lr * KVSTR + lseg * 32) * 4;
        const float* kp = kbase + goff;
        const float* vp = vbase + goff;
        #pragma unroll
        for (int i = 0; i < 8; i++) {
            cpasync16(sk + i * 16, kp + i * 4);
            cpasync16(sv + i * 16, vp + i * 4);
        }
        CPASYNC_COMMIT();
    };

    const int tq = tid & 15;       // S: q cols tq*4..+3
    const int tk = tid >> 4;       // S: k rows tk*4..+3
    const int tyO = tid >> 4;      // PV: q rows tyO*4..+3
    const int txO = tid & 15;      // PV: d cols txO*8..+7
    const int sr = tid >> 2, ssub = tid & 3;   // softmax: row, 16-k segment

    ull accO[4][4];
    #pragma unroll
    for (int i = 0; i < 4; i++)
        #pragma unroll
        for (int j = 0; j < 4; j++) accO[i][j] = 0ull;

    loadKV(0, 0);

    for (int t = 0; t < nt; t++) {
        const int buf = t & 1;
        if (t + 1 < nt) { loadKV(buf ^ 1, t + 1); CPASYNC_WAIT1(); }
        else            { CPASYNC_WAIT0(); }
        __syncthreads();   // tile ready; prior PV done with sS

        // ---- S = Q·K^T ----
        {
            const float* sK = fs + OFF_K + buf * BKT * KVSTR;
            ull accS[2][4];
            #pragma unroll
            for (int a = 0; a < 2; a++)
                #pragma unroll
                for (int b = 0; b < 4; b++) accS[a][b] = 0ull;
            #pragma unroll 4
            for (int d = 0; d < HD; d++) {
                const ull* qp = (const ull*)(sQT + d * QTSTR + tq * 4);
                const ull q01 = qp[0], q23 = qp[1];
                #pragma unroll
                for (int i = 0; i < 4; i++) {
                    const ull kd = dup2(sK[(tk * 4 + i) * KVSTR + d]);
                    ffma2(accS[0][i], q01, kd);
                    ffma2(accS[1][i], q23, kd);
                }
            }
            #pragma unroll
            for (int i = 0; i < 4; i++) {
                const float2 f0 = unpack2(accS[0][i]);
                const float2 f1 = unpack2(accS[1][i]);
                const int kc = tk * 4 + i;
                sS[(tq * 4 + 0) * SSTR + kc] = f0.x;
                sS[(tq * 4 + 1) * SSTR + kc] = f0.y;
                sS[(tq * 4 + 2) * SSTR + kc] = f1.x;
                sS[(tq * 4 + 3) * SSTR + kc] = f1.y;
            }
        }
        __syncthreads();

        // ---- online softmax ----
        {
            float vals[16];
            float* srow = sS + sr * SSTR + ssub * 16;
            #pragma unroll
            for (int i = 0; i < 16; i += 4) {
                const float4 f4 = *(const float4*)(srow + i);
                vals[i] = f4.x; vals[i+1] = f4.y; vals[i+2] = f4.z; vals[i+3] = f4.w;
            }
            if (t == nt - 1) {   // diagonal tile: mask k > q
                #pragma unroll
                for (int i = 0; i < 16; i++)
                    if (ssub * 16 + i > sr) vals[i] = -INFINITY;
            }
            float vmax = vals[0];
            #pragma unroll
            for (int i = 1; i < 16; i++) vmax = fmaxf(vmax, vals[i]);
            vmax = fmaxf(vmax, __shfl_xor_sync(0xFFFFFFFFu, vmax, 1));
            vmax = fmaxf(vmax, __shfl_xor_sync(0xFFFFFFFFu, vmax, 2));
            const float mprev = sM[sr];
            const float mnew  = fmaxf(mprev, vmax);
            float ssum = 0.0f;
            #pragma unroll
            for (int i = 0; i < 16; i++) {
                const float p = __expf(vals[i] - mnew);
                vals[i] = p;
                ssum += p;
            }
            ssum += __shfl_xor_sync(0xFFFFFFFFu, ssum, 1);
            ssum += __shfl_xor_sync(0xFFFFFFFFu, ssum, 2);
            #pragma unroll
            for (int i = 0; i < 16; i += 4)
                *(float4*)(srow + i) = make_float4(vals[i], vals[i+1], vals[i+2], vals[i+3]);
            if (ssub == 0) {
                const float alpha = __expf(mprev - mnew);
                sL[sr] = sL[sr] * alpha + ssum;
                sM[sr] = mnew;
                sAl[sr] = alpha;
            }
        }
        __syncthreads();

        // ---- O = O*alpha + P·V ----
        {
            const float* sV = fs + OFF_V + buf * BKT * KVSTR;
            #pragma unroll
            for (int i = 0; i < 4; i++) {
                const float al = sAl[tyO * 4 + i];
                #pragma unroll
                for (int j = 0; j < 4; j++) {
                    float2 f = unpack2(accO[i][j]);
                    f.x *= al; f.y *= al;
                    ull packed;
                    asm("mov.b64 %0, {%1, %2};" : "=l"(packed) : "f"(f.x), "f"(f.y));
                    accO[i][j] = packed;
                }
            }
            #pragma unroll 2
            for (int kk = 0; kk < BKT; kk++) {
                const ull* vrow = (const ull*)(sV + kk * KVSTR + txO * 8);
                const ull v0 = vrow[0], v1 = vrow[1], v2 = vrow[2], v3 = vrow[3];
                #pragma unroll
                for (int i = 0; i < 4; i++) {
                    const ull pd = dup2(sS[(tyO * 4 + i) * SSTR + kk]);
                    ffma2(accO[i][0], pd, v0);
                    ffma2(accO[i][1], pd, v1);
                    ffma2(accO[i][2], pd, v2);
                    ffma2(accO[i][3], pd, v3);
                }
            }
        }
        __syncthreads();   // protect sV/sS before next tile's loads/writes
    }

    // ---- normalize and write O ----
    #pragma unroll
    for (int i = 0; i < 4; i++) {
        const int r = tyO * 4 + i;
        const float inv = 1.0f / sL[r];
        float o[8];
        #pragma unroll
        for (int j = 0; j < 4; j++) {
            const float2 f = unpack2(accO[i][j]);
            o[2 * j]     = f.x * inv;
            o[2 * j + 1] = f.y * inv;
        }
        float* cp = ctx + (size_t)(q0 + r) * (NH * HD) + h * HD + txO * 8;
        *(float4*)cp       = make_float4(o[0], o[1], o[2], o[3]);
        *(float4*)(cp + 4) = make_float4(o[4], o[5], o[6], o[7]);
    }
}

// ---------------------------------------------------------------------------
extern "C" void kernel_launch(void* const* d_in, const int* in_sizes, int n_in,
                              void* d_out, int out_size)
{
    const float* x    = (const float*)d_in[0];
    const float* Wq   = (const float*)d_in[1];
    const float* Wk   = (const float*)d_in[2];
    const float* Wv   = (const float*)d_in[3];
    const float* Wo   = (const float*)d_in[4];
    const float* cosT = (const float*)d_in[5];
    const float* sinT = (const float*)d_in[6];
    float* out = (float*)d_out;

    float* q   = g_q;
    float* k   = g_k;
    float* v   = g_v;
    float* ctx = g_ctx;

    cudaFuncSetAttribute(gemm_f32x2<true>,  cudaFuncAttributeMaxDynamicSharedMemorySize, GEMM_SMEM);
    cudaFuncSetAttribute(gemm_f32x2<false>, cudaFuncAttributeMaxDynamicSharedMemorySize, GEMM_SMEM);
    cudaFuncSetAttribute(flash_kernel,      cudaFuncAttributeMaxDynamicSharedMemorySize, FA_SMEM);

    const dim3 blk(256);

    // QKV projections (NT) — proven R9 path
    gemm_f32x2<true><<<dim3(16, 16, 1), blk, GEMM_SMEM>>>(
        x, Wq, q, SEQ, 2048, HID, HID, HID, 2048, 0, 0, 0, 1, 0, 0);
    gemm_f32x2<true><<<dim3(8, 16, 1), blk, GEMM_SMEM>>>(
        x, Wk, k, SEQ, 1024, HID, HID, HID, 1024, 0, 0, 0, 1, 0, 0);
    gemm_f32x2<true><<<dim3(8, 16, 1), blk, GEMM_SMEM>>>(
        x, Wv, v, SEQ, 1024, HID, HID, HID, 1024, 0, 0, 0, 1, 0, 0);

    // RoPE on Q (16 heads) and K (8 heads) — proven R9 path
    {
        const int tq = SEQ * NH * (HD / 2);
        rope_kernel<<<(tq + 255) / 256, blk>>>(q, cosT, sinT, NH);
        const int tk = SEQ * NKV * (HD / 2);
        rope_kernel<<<(tk + 255) / 256, blk>>>(k, cosT, sinT, NKV);
    }

    // Flash attention (causal, GQA 2:1, applies 1/sqrt(128) internally)
    flash_kernel<<<dim3(SEQ / BQ, NH), blk, FA_SMEM>>>(q, k, v, ctx);

    // out = ctx @ Wo^T  (NT) — proven R9 path
    gemm_f32x2<true><<<dim3(16, 16, 1), blk, GEMM_SMEM>>>(
        ctx, Wo, out, SEQ, HID, NH * HD, NH * HD, NH * HD, HID, 0, 0, 0, 1, 0, 0);
}

// round 13
// speedup vs baseline: 3.1222x; 1.0009x over previous
#include <cuda_runtime.h>
#include <math.h>
#include <stdint.h>

#define SEQ 2048
#define HID 2048
#define NH  16
#define NKV 8
#define HD  128

typedef unsigned long long ull;

// Scratch (allocation-free: __device__ globals).
// RULE: these symbols are ONLY touched from host code (kernel_launch), which
// passes the decayed pointers to every kernel. No kernel references them
// directly — mixing device-symbol and host-decayed addressing caused the
// R10/R12 correctness failures.
__device__ float g_q[(size_t)SEQ * NH * HD];
__device__ float g_k[(size_t)SEQ * NKV * HD];
__device__ float g_v[(size_t)SEQ * NKV * HD];
__device__ float g_ctx[(size_t)SEQ * NH * HD];

// ---------------------------------------------------------------------------
// packed f32x2 helpers
// ---------------------------------------------------------------------------
__device__ __forceinline__ void ffma2(ull& acc, ull a, ull b) {
    asm("fma.rn.f32x2 %0, %1, %2, %0;" : "+l"(acc) : "l"(a), "l"(b));
}
__device__ __forceinline__ ull dup2(float v) {
    ull r;
    asm("mov.b64 %0, {%1, %1};" : "=l"(r) : "f"(v));
    return r;
}
__device__ __forceinline__ float2 unpack2(ull v) {
    float2 f;
    asm("mov.b64 {%0, %1}, %2;" : "=f"(f.x), "=f"(f.y) : "l"(v));
    return f;
}
__device__ __forceinline__ void cpasync16(uint32_t s, const void* g) {
    asm volatile("cp.async.cg.shared.global [%0], [%1], 16;\n" :: "r"(s), "l"(g));
}
#define CPASYNC_COMMIT() asm volatile("cp.async.commit_group;\n" ::: "memory")
#define CPASYNC_WAIT0()  asm volatile("cp.async.wait_group 0;\n" ::: "memory")
#define CPASYNC_WAIT1()  asm volatile("cp.async.wait_group 1;\n" ::: "memory")

// ---------------------------------------------------------------------------
// GEMM tile constants (proven R9 core)
// ---------------------------------------------------------------------------
#define BKG 16
#define ADUP_W 256
#define BS_W   132
#define STAGE_F (BKG * ADUP_W + BKG * BS_W)
#define GEMM_SMEM (2 * STAGE_F * 4)

// ---------------------------------------------------------------------------
// Fused QKV projection GEMM (NT). Grid (32, 16).
// bx <16: Q n-tiles; 16..23: K; 24..31: V. GEMM body identical to R9 core.
// Output buffers arrive as kernel ARGUMENTS (host-decayed pointers).
// ---------------------------------------------------------------------------
__global__ __launch_bounds__(256, 2)
void gemm_qkv(const float* __restrict__ x,
              const float* __restrict__ Wq, const float* __restrict__ Wk,
              const float* __restrict__ Wv,
              float* __restrict__ qo, float* __restrict__ ko,
              float* __restrict__ vo)
{
    extern __shared__ float smf[];

    const int bx = blockIdx.x;
    const float* B;
    float* out;
    int ldc, nc0;
    if (bx < 16)      { B = Wq + (size_t)bx * 128 * 2048;        out = qo; ldc = 2048; nc0 = bx * 128; }
    else if (bx < 24) { B = Wk + (size_t)(bx - 16) * 128 * 2048; out = ko; ldc = 1024; nc0 = (bx - 16) * 128; }
    else              { B = Wv + (size_t)(bx - 24) * 128 * 2048; out = vo; ldc = 1024; nc0 = (bx - 24) * 128; }

    const int m0 = blockIdx.y * 128;
    const int tid = threadIdx.x;
    const int tx  = tid & 15;
    const int ty  = tid >> 4;
    const int gr  = tid >> 1;
    const int gk  = (tid & 1) * 8;

    ull acc[8][4];
    #pragma unroll
    for (int i = 0; i < 8; i++)
        #pragma unroll
        for (int j = 0; j < 4; j++) acc[i][j] = 0ull;

    float4 aR0, aR1, bR0, bR1;

    auto ldg_stage = [&](int k0) {
        const float* ap = x + (long long)(m0 + gr) * 2048 + k0 + gk;
        aR0 = *(const float4*)ap;
        aR1 = *(const float4*)(ap + 4);
        const float* bp = B + (long long)gr * 2048 + k0 + gk;
        bR0 = *(const float4*)bp;
        bR1 = *(const float4*)(bp + 4);
    };
    auto sts_stage = [&](int buf) {
        float* sA_ = smf + buf * STAGE_F;
        float* sB_ = sA_ + BKG * ADUP_W;
        ull* sAd = (ull*)sA_;
        sAd[(gk + 0) * 128 + gr] = dup2(aR0.x);
        sAd[(gk + 1) * 128 + gr] = dup2(aR0.y);
        sAd[(gk + 2) * 128 + gr] = dup2(aR0.z);
        sAd[(gk + 3) * 128 + gr] = dup2(aR0.w);
        sAd[(gk + 4) * 128 + gr] = dup2(aR1.x);
        sAd[(gk + 5) * 128 + gr] = dup2(aR1.y);
        sAd[(gk + 6) * 128 + gr] = dup2(aR1.z);
        sAd[(gk + 7) * 128 + gr] = dup2(aR1.w);
        sB_[(gk + 0) * BS_W + gr] = bR0.x;
        sB_[(gk + 1) * BS_W + gr] = bR0.y;
        sB_[(gk + 2) * BS_W + gr] = bR0.z;
        sB_[(gk + 3) * BS_W + gr] = bR0.w;
        sB_[(gk + 4) * BS_W + gr] = bR1.x;
        sB_[(gk + 5) * BS_W + gr] = bR1.y;
        sB_[(gk + 6) * BS_W + gr] = bR1.z;
        sB_[(gk + 7) * BS_W + gr] = bR1.w;
    };

    ldg_stage(0);
    sts_stage(0);
    __syncthreads();

    int buf = 0;
    for (int it = 0; it < 128; it++) {
        const bool hasNext = (it + 1) < 128;
        if (hasNext) ldg_stage((it + 1) * BKG);

        const ull*   Ad = (const ull*)(smf + buf * STAGE_F);
        const float* Bf = smf + buf * STAGE_F + BKG * ADUP_W;

        #pragma unroll
        for (int kk = 0; kk < BKG; kk++) {
            const ull* arow = Ad + kk * 128;
            const ull* brow = (const ull*)(Bf + kk * BS_W);
            ull aP[8], bP[4];
            #pragma unroll
            for (int i = 0; i < 4; i++) aP[i]     = arow[ty * 4 + i];
            #pragma unroll
            for (int i = 0; i < 4; i++) aP[4 + i] = arow[64 + ty * 4 + i];
            bP[0] = brow[tx * 2];
            bP[1] = brow[tx * 2 + 1];
            bP[2] = brow[32 + tx * 2];
            bP[3] = brow[32 + tx * 2 + 1];
            #pragma unroll
            for (int mi = 0; mi < 8; mi++)
                #pragma unroll
                for (int np = 0; np < 4; np++)
                    ffma2(acc[mi][np], aP[mi], bP[np]);
        }

        if (hasNext) sts_stage(buf ^ 1);
        __syncthreads();
        buf ^= 1;
    }

    #pragma unroll
    for (int mi = 0; mi < 8; mi++) {
        const int m = (mi < 4) ? (ty * 4 + mi) : (64 + ty * 4 + mi - 4);
        float* crow = out + (long long)(m0 + m) * ldc + nc0;
        const float2 p0 = unpack2(acc[mi][0]);
        const float2 p1 = unpack2(acc[mi][1]);
        const float2 p2 = unpack2(acc[mi][2]);
        const float2 p3 = unpack2(acc[mi][3]);
        *(float4*)(crow + tx * 4)      = make_float4(p0.x, p0.y, p1.x, p1.y);
        *(float4*)(crow + 64 + tx * 4) = make_float4(p2.x, p2.y, p3.x, p3.y);
    }
}

// ---------------------------------------------------------------------------
// Generic NT GEMM (proven R9 core) — used for the output projection.
// ---------------------------------------------------------------------------
__global__ __launch_bounds__(256, 2)
void gemm_nt(const float* __restrict__ A, const float* __restrict__ B,
             float* __restrict__ C, int K, int lda, int ldb, int ldc)
{
    extern __shared__ float smf[];
    const int m0 = blockIdx.y * 128;
    const int n0 = blockIdx.x * 128;
    const int nIter = K / BKG;

    const int tid = threadIdx.x;
    const int tx  = tid & 15;
    const int ty  = tid >> 4;
    const int gr  = tid >> 1;
    const int gk  = (tid & 1) * 8;

    ull acc[8][4];
    #pragma unroll
    for (int i = 0; i < 8; i++)
        #pragma unroll
        for (int j = 0; j < 4; j++) acc[i][j] = 0ull;

    float4 aR0, aR1, bR0, bR1;

    auto ldg_stage = [&](int k0) {
        const float* ap = A + (long long)(m0 + gr) * lda + k0 + gk;
        aR0 = *(const float4*)ap;
        aR1 = *(const float4*)(ap + 4);
        const float* bp = B + (long long)(n0 + gr) * ldb + k0 + gk;
        bR0 = *(const float4*)bp;
        bR1 = *(const float4*)(bp + 4);
    };
    auto sts_stage = [&](int buf) {
        float* sA_ = smf + buf * STAGE_F;
        float* sB_ = sA_ + BKG * ADUP_W;
        ull* sAd = (ull*)sA_;
        sAd[(gk + 0) * 128 + gr] = dup2(aR0.x);
        sAd[(gk + 1) * 128 + gr] = dup2(aR0.y);
        sAd[(gk + 2) * 128 + gr] = dup2(aR0.z);
        sAd[(gk + 3) * 128 + gr] = dup2(aR0.w);
        sAd[(gk + 4) * 128 + gr] = dup2(aR1.x);
        sAd[(gk + 5) * 128 + gr] = dup2(aR1.y);
        sAd[(gk + 6) * 128 + gr] = dup2(aR1.z);
        sAd[(gk + 7) * 128 + gr] = dup2(aR1.w);
        sB_[(gk + 0) * BS_W + gr] = bR0.x;
        sB_[(gk + 1) * BS_W + gr] = bR0.y;
        sB_[(gk + 2) * BS_W + gr] = bR0.z;
        sB_[(gk + 3) * BS_W + gr] = bR0.w;
        sB_[(gk + 4) * BS_W + gr] = bR1.x;
        sB_[(gk + 5) * BS_W + gr] = bR1.y;
        sB_[(gk + 6) * BS_W + gr] = bR1.z;
        sB_[(gk + 7) * BS_W + gr] = bR1.w;
    };

    ldg_stage(0);
    sts_stage(0);
    __syncthreads();

    int buf = 0;
    for (int it = 0; it < nIter; it++) {
        const bool hasNext = (it + 1) < nIter;
        if (hasNext) ldg_stage((it + 1) * BKG);

        const ull*   Ad = (const ull*)(smf + buf * STAGE_F);
        const float* Bf = smf + buf * STAGE_F + BKG * ADUP_W;

        #pragma unroll
        for (int kk = 0; kk < BKG; kk++) {
            const ull* arow = Ad + kk * 128;
            const ull* brow = (const ull*)(Bf + kk * BS_W);
            ull aP[8], bP[4];
            #pragma unroll
            for (int i = 0; i < 4; i++) aP[i]     = arow[ty * 4 + i];
            #pragma unroll
            for (int i = 0; i < 4; i++) aP[4 + i] = arow[64 + ty * 4 + i];
            bP[0] = brow[tx * 2];
            bP[1] = brow[tx * 2 + 1];
            bP[2] = brow[32 + tx * 2];
            bP[3] = brow[32 + tx * 2 + 1];
            #pragma unroll
            for (int mi = 0; mi < 8; mi++)
                #pragma unroll
                for (int np = 0; np < 4; np++)
                    ffma2(acc[mi][np], aP[mi], bP[np]);
        }

        if (hasNext) sts_stage(buf ^ 1);
        __syncthreads();
        buf ^= 1;
    }

    #pragma unroll
    for (int mi = 0; mi < 8; mi++) {
        const int m = (mi < 4) ? (ty * 4 + mi) : (64 + ty * 4 + mi - 4);
        float* crow = C + (long long)(m0 + m) * ldc + n0;
        const float2 p0 = unpack2(acc[mi][0]);
        const float2 p1 = unpack2(acc[mi][1]);
        const float2 p2 = unpack2(acc[mi][2]);
        const float2 p3 = unpack2(acc[mi][3]);
        *(float4*)(crow + tx * 4)      = make_float4(p0.x, p0.y, p1.x, p1.y);
        *(float4*)(crow + 64 + tx * 4) = make_float4(p2.x, p2.y, p3.x, p3.y);
    }
}

// ---------------------------------------------------------------------------
// Combined RoPE for Q (16 heads) and K (8 heads), in-place. One launch.
// ---------------------------------------------------------------------------
#define QROPE_N (SEQ * NH * (HD / 2))
#define KROPE_N (SEQ * NKV * (HD / 2))

__global__ void rope_both_kernel(float* __restrict__ q, float* __restrict__ k,
                                 const float* __restrict__ cosT,
                                 const float* __restrict__ sinT)
{
    int idx = blockIdx.x * blockDim.x + threadIdx.x;
    float* t;
    int heads;
    if (idx < QROPE_N) { t = q; heads = NH; }
    else {
        idx -= QROPE_N;
        if (idx >= KROPE_N) return;
        t = k; heads = NKV;
    }
    const int d = idx % (HD / 2);
    const int h = (idx / (HD / 2)) % heads;
    const int s = idx / ((HD / 2) * heads);

    const float c1 = cosT[s * HD + d];
    const float s1 = sinT[s * HD + d];
    const float c2 = cosT[s * HD + d + HD / 2];
    const float s2 = sinT[s * HD + d + HD / 2];

    float* row = t + (long long)s * heads * HD + h * HD;
    const float x1 = row[d];
    const float x2 = row[d + HD / 2];
    row[d]          = x1 * c1 - x2 * s1;
    row[d + HD / 2] = x2 * c2 + x1 * s2;
}

// ---------------------------------------------------------------------------
// Flash attention (proven R11): per CTA one (head, 64 q-rows). Online softmax,
// exact causal mask, 64-row K/V tiles double-buffered. Applies 1/sqrt(128).
// ---------------------------------------------------------------------------
#define BQ 64
#define BKT 64
#define KVSTR 132
#define QTSTR 68
#define SSTR 68
#define OFF_QT 0
#define OFF_K  (OFF_QT + 128 * QTSTR)
#define OFF_V  (OFF_K + 2 * BKT * KVSTR)
#define OFF_S  (OFF_V + 2 * BKT * KVSTR)
#define OFF_M  (OFF_S + BQ * SSTR)
#define OFF_L  (OFF_M + 64)
#define OFF_AL (OFF_L + 64)
#define FA_SMEM ((OFF_AL + 64) * 4)

__global__ __launch_bounds__(256, 1)
void flash_kernel(const float* __restrict__ q, const float* __restrict__ k,
                  const float* __restrict__ v, float* __restrict__ ctx)
{
    extern __shared__ float fs[];
    float* sQT = fs + OFF_QT;
    float* sS  = fs + OFF_S;
    float* sM  = fs + OFF_M;
    float* sL  = fs + OFF_L;
    float* sAl = fs + OFF_AL;

    const int qt = (int)gridDim.x - 1 - (int)blockIdx.x;
    const int h  = blockIdx.y;
    const int q0 = qt * BQ;
    const int tid = threadIdx.x;
    const int nt = qt + 1;
    const float qscale = 0.08838834764831845f;

    const uint32_t sbase = (uint32_t)__cvta_generic_to_shared(fs);

    {
        const int r = tid >> 2, seg = tid & 3;
        const float* gp = q + (size_t)(q0 + r) * (NH * HD) + h * HD + seg * 32;
        #pragma unroll
        for (int i = 0; i < 8; i++) {
            const float4 f4 = ((const float4*)gp)[i];
            const int d = seg * 32 + i * 4;
            sQT[(d + 0) * QTSTR + r] = f4.x * qscale;
            sQT[(d + 1) * QTSTR + r] = f4.y * qscale;
            sQT[(d + 2) * QTSTR + r] = f4.z * qscale;
            sQT[(d + 3) * QTSTR + r] = f4.w * qscale;
        }
    }
    if (tid < 64) { sM[tid] = -INFINITY; sL[tid] = 0.0f; }

    const int lr = tid >> 2, lseg = tid & 3;
    const float* kbase = k + (size_t)lr * (NKV * HD) + (h >> 1) * HD + lseg * 32;
    const float* vbase = v + (size_t)lr * (NKV * HD) + (h >> 1) * HD + lseg * 32;
    auto loadKV = [&](int buf, int t) {
        const size_t goff = (size_t)t * BKT * (NKV * HD);
        const uint32_t sk = sbase + (uint32_t)(OFF_K + buf * BKT * KVSTR + lr * KVSTR + lseg * 32) * 4;
        const uint32_t sv = sbase + (uint32_t)(OFF_V + buf * BKT * KVSTR + lr * KVSTR + lseg * 32) * 4;
        const float* kp = kbase + goff;
        const float* vp = vbase + goff;
        #pragma unroll
        for (int i = 0; i < 8; i++) {
            cpasync16(sk + i * 16, kp + i * 4);
            cpasync16(sv + i * 16, vp + i * 4);
        }
        CPASYNC_COMMIT();
    };

    const int tq = tid & 15;
    const int tk = tid >> 4;
    const int tyO = tid >> 4;
    const int txO = tid & 15;
    const int sr = tid >> 2, ssub = tid & 3;

    ull accO[4][4];
    #pragma unroll
    for (int i = 0; i < 4; i++)
        #pragma unroll
        for (int j = 0; j < 4; j++) accO[i][j] = 0ull;

    loadKV(0, 0);

    for (int t = 0; t < nt; t++) {
        const int buf = t & 1;
        if (t + 1 < nt) { loadKV(buf ^ 1, t + 1); CPASYNC_WAIT1(); }
        else            { CPASYNC_WAIT0(); }
        __syncthreads();

        {
            const float* sK = fs + OFF_K + buf * BKT * KVSTR;
            ull accS[2][4];
            #pragma unroll
            for (int a = 0; a < 2; a++)
                #pragma unroll
                for (int b = 0; b < 4; b++) accS[a][b] = 0ull;
            #pragma unroll 4
            for (int d = 0; d < HD; d++) {
                const ull* qp = (const ull*)(sQT + d * QTSTR + tq * 4);
                const ull q01 = qp[0], q23 = qp[1];
                #pragma unroll
                for (int i = 0; i < 4; i++) {
                    const ull kd = dup2(sK[(tk * 4 + i) * KVSTR + d]);
                    ffma2(accS[0][i], q01, kd);
                    ffma2(accS[1][i], q23, kd);
                }
            }
            #pragma unroll
            for (int i = 0; i < 4; i++) {
                const float2 f0 = unpack2(accS[0][i]);
                const float2 f1 = unpack2(accS[1][i]);
                const int kc = tk * 4 + i;
                sS[(tq * 4 + 0) * SSTR + kc] = f0.x;
                sS[(tq * 4 + 1) * SSTR + kc] = f0.y;
                sS[(tq * 4 + 2) * SSTR + kc] = f1.x;
                sS[(tq * 4 + 3) * SSTR + kc] = f1.y;
            }
        }
        __syncthreads();

        {
            float vals[16];
            float* srow = sS + sr * SSTR + ssub * 16;
            #pragma unroll
            for (int i = 0; i < 16; i += 4) {
                const float4 f4 = *(const float4*)(srow + i);
                vals[i] = f4.x; vals[i+1] = f4.y; vals[i+2] = f4.z; vals[i+3] = f4.w;
            }
            if (t == nt - 1) {
                #pragma unroll
                for (int i = 0; i < 16; i++)
                    if (ssub * 16 + i > sr) vals[i] = -INFINITY;
            }
            float vmax = vals[0];
            #pragma unroll
            for (int i = 1; i < 16; i++) vmax = fmaxf(vmax, vals[i]);
            vmax = fmaxf(vmax, __shfl_xor_sync(0xFFFFFFFFu, vmax, 1));
            vmax = fmaxf(vmax, __shfl_xor_sync(0xFFFFFFFFu, vmax, 2));
            const float mprev = sM[sr];
            const float mnew  = fmaxf(mprev, vmax);
            float ssum = 0.0f;
            #pragma unroll
            for (int i = 0; i < 16; i++) {
                const float p = __expf(vals[i] - mnew);
                vals[i] = p;
                ssum += p;
            }
            ssum += __shfl_xor_sync(0xFFFFFFFFu, ssum, 1);
            ssum += __shfl_xor_sync(0xFFFFFFFFu, ssum, 2);
            #pragma unroll
            for (int i = 0; i < 16; i += 4)
                *(float4*)(srow + i) = make_float4(vals[i], vals[i+1], vals[i+2], vals[i+3]);
            if (ssub == 0) {
                const float alpha = __expf(mprev - mnew);
                sL[sr] = sL[sr] * alpha + ssum;
                sM[sr] = mnew;
                sAl[sr] = alpha;
            }
        }
        __syncthreads();

        {
            const float* sV = fs + OFF_V + buf * BKT * KVSTR;
            #pragma unroll
            for (int i = 0; i < 4; i++) {
                const float al = sAl[tyO * 4 + i];
                #pragma unroll
                for (int j = 0; j < 4; j++) {
                    float2 f = unpack2(accO[i][j]);
                    f.x *= al; f.y *= al;
                    ull packed;
                    asm("mov.b64 %0, {%1, %2};" : "=l"(packed) : "f"(f.x), "f"(f.y));
                    accO[i][j] = packed;
                }
            }
            #pragma unroll 2
            for (int kk = 0; kk < BKT; kk++) {
                const ull* vrow = (const ull*)(sV + kk * KVSTR + txO * 8);
                const ull v0 = vrow[0], v1 = vrow[1], v2 = vrow[2], v3 = vrow[3];
                #pragma unroll
                for (int i = 0; i < 4; i++) {
                    const ull pd = dup2(sS[(tyO * 4 + i) * SSTR + kk]);
                    ffma2(accO[i][0], pd, v0);
                    ffma2(accO[i][1], pd, v1);
                    ffma2(accO[i][2], pd, v2);
                    ffma2(accO[i][3], pd, v3);
                }
            }
        }
        __syncthreads();
    }

    #pragma unroll
    for (int i = 0; i < 4; i++) {
        const int r = tyO * 4 + i;
        const float inv = 1.0f / sL[r];
        float o[8];
        #pragma unroll
        for (int j = 0; j < 4; j++) {
            const float2 f = unpack2(accO[i][j]);
            o[2 * j]     = f.x * inv;
            o[2 * j + 1] = f.y * inv;
        }
        float* cp = ctx + (size_t)(q0 + r) * (NH * HD) + h * HD + txO * 8;
        *(float4*)cp       = make_float4(o[0], o[1], o[2], o[3]);
        *(float4*)(cp + 4) = make_float4(o[4], o[5], o[6], o[7]);
    }
}

// ---------------------------------------------------------------------------
extern "C" void kernel_launch(void* const* d_in, const int* in_sizes, int n_in,
                              void* d_out, int out_size)
{
    const float* x    = (const float*)d_in[0];
    const float* Wq   = (const float*)d_in[1];
    const float* Wk   = (const float*)d_in[2];
    const float* Wv   = (const float*)d_in[3];
    const float* Wo   = (const float*)d_in[4];
    const float* cosT = (const float*)d_in[5];
    const float* sinT = (const float*)d_in[6];
    float* out = (float*)d_out;

    // host-decayed scratch pointers — the ONLY place g_* symbols are touched
    float* q   = g_q;
    float* k   = g_k;
    float* v   = g_v;
    float* ctx = g_ctx;

    cudaFuncSetAttribute(gemm_qkv,     cudaFuncAttributeMaxDynamicSharedMemorySize, GEMM_SMEM);
    cudaFuncSetAttribute(gemm_nt,      cudaFuncAttributeMaxDynamicSharedMemorySize, GEMM_SMEM);
    cudaFuncSetAttribute(flash_kernel, cudaFuncAttributeMaxDynamicSharedMemorySize, FA_SMEM);

    const dim3 blk(256);

    // 1) fused QKV projections (one dense launch: 512 CTAs)
    gemm_qkv<<<dim3(32, 16), blk, GEMM_SMEM>>>(x, Wq, Wk, Wv, q, k, v);

    // 2) RoPE on Q and K in one launch
    {
        const int total = QROPE_N + KROPE_N;
        rope_both_kernel<<<(total + 255) / 256, blk>>>(q, k, cosT, sinT);
    }

    // 3) flash attention (causal, GQA 2:1)
    flash_kernel<<<dim3(SEQ / BQ, NH), blk, FA_SMEM>>>(q, k, v, ctx);

    // 4) out = ctx @ Wo^T
    gemm_nt<<<dim3(16, 16), blk, GEMM_SMEM>>>(ctx, Wo, out, NH * HD,
                                              NH * HD, NH * HD, HID);
}

// round 14
// speedup vs baseline: 3.2185x; 1.0308x over previous
#include <cuda_runtime.h>
#include <math.h>
#include <stdint.h>

#define SEQ 2048
#define HID 2048
#define NH  16
#define NKV 8
#define HD  128

typedef unsigned long long ull;

// Scratch (allocation-free: __device__ globals).
// RULE: only touched from host code in kernel_launch (decayed pointers passed
// as kernel args). Mixing device-symbol and host-decayed addressing caused the
// R10/R12 correctness failures.
__device__ float g_q[(size_t)SEQ * NH * HD];
__device__ float g_k[(size_t)SEQ * NKV * HD];
__device__ float g_v[(size_t)SEQ * NKV * HD];
__device__ float g_ctx[(size_t)SEQ * NH * HD];

// ---------------------------------------------------------------------------
// packed f32x2 helpers
// ---------------------------------------------------------------------------
__device__ __forceinline__ void ffma2(ull& acc, ull a, ull b) {
    asm("fma.rn.f32x2 %0, %1, %2, %0;" : "+l"(acc) : "l"(a), "l"(b));
}
__device__ __forceinline__ ull dup2(float v) {
    ull r;
    asm("mov.b64 %0, {%1, %1};" : "=l"(r) : "f"(v));
    return r;
}
__device__ __forceinline__ float2 unpack2(ull v) {
    float2 f;
    asm("mov.b64 {%0, %1}, %2;" : "=f"(f.x), "=f"(f.y) : "l"(v));
    return f;
}
__device__ __forceinline__ void cpasync16(uint32_t s, const void* g) {
    asm volatile("cp.async.cg.shared.global [%0], [%1], 16;\n" :: "r"(s), "l"(g));
}
#define CPASYNC_COMMIT() asm volatile("cp.async.commit_group;\n" ::: "memory")
#define CPASYNC_WAIT0()  asm volatile("cp.async.wait_group 0;\n" ::: "memory")
#define CPASYNC_WAIT1()  asm volatile("cp.async.wait_group 1;\n" ::: "memory")

// ---------------------------------------------------------------------------
// GEMM core v2: 128x128 CTA tile, 512 threads, BK=32, double-buffered.
// Thread (tx=tid&31, ty=tid>>5): m rows ty*8..+7, n cols tx*4..+3.
// A stored dup'd in smem ((a,a) ull pairs, k-major rows of 128 ull);
// B stored transposed [k][n] (BS_W-float rows).
// Per kk: 4x LDS.128 A (warp-broadcast) + 1x LDS.128 B + 16 FFMA2.
// acc = 16 ull (32 regs) -> large ptxas scheduling headroom.
// ---------------------------------------------------------------------------
#define BKG 32
#define ADUP_W 256                         // floats per A-dup k-row (=128 ull)
#define BS_W   132                         // floats per B k-row (16B-aligned: 528B)
#define STAGE_F (BKG * ADUP_W + BKG * BS_W)   // 12416 floats
#define GEMM_SMEM (2 * STAGE_F * 4)           // 99328 bytes

__device__ __forceinline__
void gemm_core(const float* __restrict__ A, const float* __restrict__ Btile,
               float* __restrict__ Ctile, int lda, int ldb, int ldc,
               int m0, int K, float* smf)
{
    const int tid  = threadIdx.x;
    const int tx   = tid & 31;
    const int ty   = tid >> 5;
    const int grow = tid >> 2;            // 0..127
    const int gc8  = (tid & 3) * 8;       // 0,8,16,24

    ull acc[8][2];
    #pragma unroll
    for (int i = 0; i < 8; i++) { acc[i][0] = 0ull; acc[i][1] = 0ull; }

    float4 aR0, aR1, bR0, bR1;

    auto ldg_stage = [&](int k0) {
        const float* ap = A + (long long)(m0 + grow) * lda + k0 + gc8;
        aR0 = *(const float4*)ap;
        aR1 = *(const float4*)(ap + 4);
        const float* bp = Btile + (long long)grow * ldb + k0 + gc8;
        bR0 = *(const float4*)bp;
        bR1 = *(const float4*)(bp + 4);
    };
    auto sts_stage = [&](int buf) {
        ull*   sAd = (ull*)(smf + buf * STAGE_F);
        float* sB  = smf + buf * STAGE_F + BKG * ADUP_W;
        sAd[(gc8 + 0) * 128 + grow] = dup2(aR0.x);
        sAd[(gc8 + 1) * 128 + grow] = dup2(aR0.y);
        sAd[(gc8 + 2) * 128 + grow] = dup2(aR0.z);
        sAd[(gc8 + 3) * 128 + grow] = dup2(aR0.w);
        sAd[(gc8 + 4) * 128 + grow] = dup2(aR1.x);
        sAd[(gc8 + 5) * 128 + grow] = dup2(aR1.y);
        sAd[(gc8 + 6) * 128 + grow] = dup2(aR1.z);
        sAd[(gc8 + 7) * 128 + grow] = dup2(aR1.w);
        sB[(gc8 + 0) * BS_W + grow] = bR0.x;
        sB[(gc8 + 1) * BS_W + grow] = bR0.y;
        sB[(gc8 + 2) * BS_W + grow] = bR0.z;
        sB[(gc8 + 3) * BS_W + grow] = bR0.w;
        sB[(gc8 + 4) * BS_W + grow] = bR1.x;
        sB[(gc8 + 5) * BS_W + grow] = bR1.y;
        sB[(gc8 + 6) * BS_W + grow] = bR1.z;
        sB[(gc8 + 7) * BS_W + grow] = bR1.w;
    };

    ldg_stage(0);
    sts_stage(0);
    __syncthreads();

    const int nIter = K / BKG;
    int buf = 0;
    for (int it = 0; it < nIter; it++) {
        const bool hasNext = (it + 1) < nIter;
        if (hasNext) ldg_stage((it + 1) * BKG);

        const ull*   Ad = (const ull*)(smf + buf * STAGE_F);
        const float* Bf = smf + buf * STAGE_F + BKG * ADUP_W;

        #pragma unroll
        for (int kk = 0; kk < BKG; kk++) {
            const ull* arow = Ad + kk * 128 + ty * 8;
            const ulonglong2 a01 = *(const ulonglong2*)(arow + 0);
            const ulonglong2 a23 = *(const ulonglong2*)(arow + 2);
            const ulonglong2 a45 = *(const ulonglong2*)(arow + 4);
            const ulonglong2 a67 = *(const ulonglong2*)(arow + 6);
            const ulonglong2 b   = *(const ulonglong2*)((const ull*)(Bf + kk * BS_W) + tx * 2);
            ffma2(acc[0][0], a01.x, b.x); ffma2(acc[0][1], a01.x, b.y);
            ffma2(acc[1][0], a01.y, b.x); ffma2(acc[1][1], a01.y, b.y);
            ffma2(acc[2][0], a23.x, b.x); ffma2(acc[2][1], a23.x, b.y);
            ffma2(acc[3][0], a23.y, b.x); ffma2(acc[3][1], a23.y, b.y);
            ffma2(acc[4][0], a45.x, b.x); ffma2(acc[4][1], a45.x, b.y);
            ffma2(acc[5][0], a45.y, b.x); ffma2(acc[5][1], a45.y, b.y);
            ffma2(acc[6][0], a67.x, b.x); ffma2(acc[6][1], a67.x, b.y);
            ffma2(acc[7][0], a67.y, b.x); ffma2(acc[7][1], a67.y, b.y);
        }

        if (hasNext) sts_stage(buf ^ 1);
        __syncthreads();
        buf ^= 1;
    }

    #pragma unroll
    for (int i = 0; i < 8; i++) {
        const float2 p0 = unpack2(acc[i][0]);
        const float2 p1 = unpack2(acc[i][1]);
        *(float4*)(Ctile + (long long)(m0 + ty * 8 + i) * ldc + tx * 4) =
            make_float4(p0.x, p0.y, p1.x, p1.y);
    }
}

// ---------------------------------------------------------------------------
// Fused QKV projection GEMM (NT). Grid (32, 16), 512 threads.
// bx <16: Q n-tiles; 16..23: K; 24..31: V.
// ---------------------------------------------------------------------------
__global__ __launch_bounds__(512, 1)
void gemm_qkv(const float* __restrict__ x,
              const float* __restrict__ Wq, const float* __restrict__ Wk,
              const float* __restrict__ Wv,
              float* __restrict__ qo, float* __restrict__ ko,
              float* __restrict__ vo)
{
    extern __shared__ float smf[];
    const int bx = blockIdx.x;
    const float* B;
    float* out;
    int ldc, nc0;
    if (bx < 16)      { B = Wq + (size_t)bx * 128 * 2048;        out = qo; ldc = 2048; nc0 = bx * 128; }
    else if (bx < 24) { B = Wk + (size_t)(bx - 16) * 128 * 2048; out = ko; ldc = 1024; nc0 = (bx - 16) * 128; }
    else              { B = Wv + (size_t)(bx - 24) * 128 * 2048; out = vo; ldc = 1024; nc0 = (bx - 24) * 128; }

    gemm_core(x, B, out + nc0, 2048, 2048, ldc, blockIdx.y * 128, 2048, smf);
}

// ---------------------------------------------------------------------------
// Output projection GEMM (NT). Grid (16, 16), 512 threads.
// ---------------------------------------------------------------------------
__global__ __launch_bounds__(512, 1)
void gemm_nt(const float* __restrict__ A, const float* __restrict__ B,
             float* __restrict__ C)
{
    extern __shared__ float smf[];
    const int n0 = blockIdx.x * 128;
    gemm_core(A, B + (size_t)n0 * 2048, C + n0, 2048, 2048, 2048,
              blockIdx.y * 128, 2048, smf);
}

// ---------------------------------------------------------------------------
// Combined RoPE for Q (16 heads) and K (8 heads), in-place. One launch.
// ---------------------------------------------------------------------------
#define QROPE_N (SEQ * NH * (HD / 2))
#define KROPE_N (SEQ * NKV * (HD / 2))

__global__ void rope_both_kernel(float* __restrict__ q, float* __restrict__ k,
                                 const float* __restrict__ cosT,
                                 const float* __restrict__ sinT)
{
    int idx = blockIdx.x * blockDim.x + threadIdx.x;
    float* t;
    int heads;
    if (idx < QROPE_N) { t = q; heads = NH; }
    else {
        idx -= QROPE_N;
        if (idx >= KROPE_N) return;
        t = k; heads = NKV;
    }
    const int d = idx % (HD / 2);
    const int h = (idx / (HD / 2)) % heads;
    const int s = idx / ((HD / 2) * heads);

    const float c1 = cosT[s * HD + d];
    const float s1 = sinT[s * HD + d];
    const float c2 = cosT[s * HD + d + HD / 2];
    const float s2 = sinT[s * HD + d + HD / 2];

    float* row = t + (long long)s * heads * HD + h * HD;
    const float x1 = row[d];
    const float x2 = row[d + HD / 2];
    row[d]          = x1 * c1 - x2 * s1;
    row[d + HD / 2] = x2 * c2 + x1 * s2;
}

// ---------------------------------------------------------------------------
// Flash attention (proven R11/R13, unchanged): per CTA one (head, 64 q-rows).
// Online softmax, exact causal mask, 64-row K/V tiles double-buffered.
// ---------------------------------------------------------------------------
#define BQ 64
#define BKT 64
#define KVSTR 132
#define QTSTR 68
#define SSTR 68
#define OFF_QT 0
#define OFF_K  (OFF_QT + 128 * QTSTR)
#define OFF_V  (OFF_K + 2 * BKT * KVSTR)
#define OFF_S  (OFF_V + 2 * BKT * KVSTR)
#define OFF_M  (OFF_S + BQ * SSTR)
#define OFF_L  (OFF_M + 64)
#define OFF_AL (OFF_L + 64)
#define FA_SMEM ((OFF_AL + 64) * 4)

__global__ __launch_bounds__(256, 1)
void flash_kernel(const float* __restrict__ q, const float* __restrict__ k,
                  const float* __restrict__ v, float* __restrict__ ctx)
{
    extern __shared__ float fs[];
    float* sQT = fs + OFF_QT;
    float* sS  = fs + OFF_S;
    float* sM  = fs + OFF_M;
    float* sL  = fs + OFF_L;
    float* sAl = fs + OFF_AL;

    const int qt = (int)gridDim.x - 1 - (int)blockIdx.x;
    const int h  = blockIdx.y;
    const int q0 = qt * BQ;
    const int tid = threadIdx.x;
    const int nt = qt + 1;
    const float qscale = 0.08838834764831845f;

    const uint32_t sbase = (uint32_t)__cvta_generic_to_shared(fs);

    {
        const int r = tid >> 2, seg = tid & 3;
        const float* gp = q + (size_t)(q0 + r) * (NH * HD) + h * HD + seg * 32;
        #pragma unroll
        for (int i = 0; i < 8; i++) {
            const float4 f4 = ((const float4*)gp)[i];
            const int d = seg * 32 + i * 4;
            sQT[(d + 0) * QTSTR + r] = f4.x * qscale;
            sQT[(d + 1) * QTSTR + r] = f4.y * qscale;
            sQT[(d + 2) * QTSTR + r] = f4.z * qscale;
            sQT[(d + 3) * QTSTR + r] = f4.w * qscale;
        }
    }
    if (tid < 64) { sM[tid] = -INFINITY; sL[tid] = 0.0f; }

    const int lr = tid >> 2, lseg = tid & 3;
    const float* kbase = k + (size_t)lr * (NKV * HD) + (h >> 1) * HD + lseg * 32;
    const float* vbase = v + (size_t)lr * (NKV * HD) + (h >> 1) * HD + lseg * 32;
    auto loadKV = [&](int buf, int t) {
        const size_t goff = (size_t)t * BKT * (NKV * HD);
        const uint32_t sk = sbase + (uint32_t)(OFF_K + buf * BKT * KVSTR + lr * KVSTR + lseg * 32) * 4;
        const uint32_t sv = sbase + (uint32_t)(OFF_V + buf * BKT * KVSTR + lr * KVSTR + lseg * 32) * 4;
        const float* kp = kbase + goff;
        const float* vp = vbase + goff;
        #pragma unroll
        for (int i = 0; i < 8; i++) {
            cpasync16(sk + i * 16, kp + i * 4);
            cpasync16(sv + i * 16, vp + i * 4);
        }
        CPASYNC_COMMIT();
    };

    const int tq = tid & 15;
    const int tk = tid >> 4;
    const int tyO = tid >> 4;
    const int txO = tid & 15;
    const int sr = tid >> 2, ssub = tid & 3;

    ull accO[4][4];
    #pragma unroll
    for (int i = 0; i < 4; i++)
        #pragma unroll
        for (int j = 0; j < 4; j++) accO[i][j] = 0ull;

    loadKV(0, 0);

    for (int t = 0; t < nt; t++) {
        const int buf = t & 1;
        if (t + 1 < nt) { loadKV(buf ^ 1, t + 1); CPASYNC_WAIT1(); }
        else            { CPASYNC_WAIT0(); }
        __syncthreads();

        {
            const float* sK = fs + OFF_K + buf * BKT * KVSTR;
            ull accS[2][4];
            #pragma unroll
            for (int a = 0; a < 2; a++)
                #pragma unroll
                for (int b = 0; b < 4; b++) accS[a][b] = 0ull;
            #pragma unroll 4
            for (int d = 0; d < HD; d++) {
                const ull* qp = (const ull*)(sQT + d * QTSTR + tq * 4);
                const ull q01 = qp[0], q23 = qp[1];
                #pragma unroll
                for (int i = 0; i < 4; i++) {
                    const ull kd = dup2(sK[(tk * 4 + i) * KVSTR + d]);
                    ffma2(accS[0][i], q01, kd);
                    ffma2(accS[1][i], q23, kd);
                }
            }
            #pragma unroll
            for (int i = 0; i < 4; i++) {
                const float2 f0 = unpack2(accS[0][i]);
                const float2 f1 = unpack2(accS[1][i]);
                const int kc = tk * 4 + i;
                sS[(tq * 4 + 0) * SSTR + kc] = f0.x;
                sS[(tq * 4 + 1) * SSTR + kc] = f0.y;
                sS[(tq * 4 + 2) * SSTR + kc] = f1.x;
                sS[(tq * 4 + 3) * SSTR + kc] = f1.y;
            }
        }
        __syncthreads();

        {
            float vals[16];
            float* srow = sS + sr * SSTR + ssub * 16;
            #pragma unroll
            for (int i = 0; i < 16; i += 4) {
                const float4 f4 = *(const float4*)(srow + i);
                vals[i] = f4.x; vals[i+1] = f4.y; vals[i+2] = f4.z; vals[i+3] = f4.w;
            }
            if (t == nt - 1) {
                #pragma unroll
                for (int i = 0; i < 16; i++)
                    if (ssub * 16 + i > sr) vals[i] = -INFINITY;
            }
            float vmax = vals[0];
            #pragma unroll
            for (int i = 1; i < 16; i++) vmax = fmaxf(vmax, vals[i]);
            vmax = fmaxf(vmax, __shfl_xor_sync(0xFFFFFFFFu, vmax, 1));
            vmax = fmaxf(vmax, __shfl_xor_sync(0xFFFFFFFFu, vmax, 2));
            const float mprev = sM[sr];
            const float mnew  = fmaxf(mprev, vmax);
            float ssum = 0.0f;
            #pragma unroll
            for (int i = 0; i < 16; i++) {
                const float p = __expf(vals[i] - mnew);
                vals[i] = p;
                ssum += p;
            }
            ssum += __shfl_xor_sync(0xFFFFFFFFu, ssum, 1);
            ssum += __shfl_xor_sync(0xFFFFFFFFu, ssum, 2);
            #pragma unroll
            for (int i = 0; i < 16; i += 4)
                *(float4*)(srow + i) = make_float4(vals[i], vals[i+1], vals[i+2], vals[i+3]);
            if (ssub == 0) {
                const float alpha = __expf(mprev - mnew);
                sL[sr] = sL[sr] * alpha + ssum;
                sM[sr] = mnew;
                sAl[sr] = alpha;
            }
        }
        __syncthreads();

        {
            const float* sV = fs + OFF_V + buf * BKT * KVSTR;
            #pragma unroll
            for (int i = 0; i < 4; i++) {
                const float al = sAl[tyO * 4 + i];
                #pragma unroll
                for (int j = 0; j < 4; j++) {
                    float2 f = unpack2(accO[i][j]);
                    f.x *= al; f.y *= al;
                    ull packed;
                    asm("mov.b64 %0, {%1, %2};" : "=l"(packed) : "f"(f.x), "f"(f.y));
                    accO[i][j] = packed;
                }
            }
            #pragma unroll 2
            for (int kk = 0; kk < BKT; kk++) {
                const ull* vrow = (const ull*)(sV + kk * KVSTR + txO * 8);
                const ull v0 = vrow[0], v1 = vrow[1], v2 = vrow[2], v3 = vrow[3];
                #pragma unroll
                for (int i = 0; i < 4; i++) {
                    const ull pd = dup2(sS[(tyO * 4 + i) * SSTR + kk]);
                    ffma2(accO[i][0], pd, v0);
                    ffma2(accO[i][1], pd, v1);
                    ffma2(accO[i][2], pd, v2);
                    ffma2(accO[i][3], pd, v3);
                }
            }
        }
        __syncthreads();
    }

    #pragma unroll
    for (int i = 0; i < 4; i++) {
        const int r = tyO * 4 + i;
        const float inv = 1.0f / sL[r];
        float o[8];
        #pragma unroll
        for (int j = 0; j < 4; j++) {
            const float2 f = unpack2(accO[i][j]);
            o[2 * j]     = f.x * inv;
            o[2 * j + 1] = f.y * inv;
        }
        float* cp = ctx + (size_t)(q0 + r) * (NH * HD) + h * HD + txO * 8;
        *(float4*)cp       = make_float4(o[0], o[1], o[2], o[3]);
        *(float4*)(cp + 4) = make_float4(o[4], o[5], o[6], o[7]);
    }
}

// ---------------------------------------------------------------------------
extern "C" void kernel_launch(void* const* d_in, const int* in_sizes, int n_in,
                              void* d_out, int out_size)
{
    const float* x    = (const float*)d_in[0];
    const float* Wq   = (const float*)d_in[1];
    const float* Wk   = (const float*)d_in[2];
    const float* Wv   = (const float*)d_in[3];
    const float* Wo   = (const float*)d_in[4];
    const float* cosT = (const float*)d_in[5];
    const float* sinT = (const float*)d_in[6];
    float* out = (float*)d_out;

    // host-decayed scratch pointers — the ONLY place g_* symbols are touched
    float* q   = g_q;
    float* k   = g_k;
    float* v   = g_v;
    float* ctx = g_ctx;

    cudaFuncSetAttribute(gemm_qkv,     cudaFuncAttributeMaxDynamicSharedMemorySize, GEMM_SMEM);
    cudaFuncSetAttribute(gemm_nt,      cudaFuncAttributeMaxDynamicSharedMemorySize, GEMM_SMEM);
    cudaFuncSetAttribute(flash_kernel, cudaFuncAttributeMaxDynamicSharedMemorySize, FA_SMEM);

    // 1) fused QKV projections (512 CTAs x 512 threads)
    gemm_qkv<<<dim3(32, 16), dim3(512), GEMM_SMEM>>>(x, Wq, Wk, Wv, q, k, v);

    // 2) RoPE on Q and K in one launch
    {
        const int total = QROPE_N + KROPE_N;
        rope_both_kernel<<<(total + 255) / 256, dim3(256)>>>(q, k, cosT, sinT);
    }

    // 3) flash attention (causal, GQA 2:1)
    flash_kernel<<<dim3(SEQ / BQ, NH), dim3(256), FA_SMEM>>>(q, k, v, ctx);

    // 4) out = ctx @ Wo^T
    gemm_nt<<<dim3(16, 16), dim3(512), GEMM_SMEM>>>(ctx, Wo, out);
}